// round 1
// baseline (speedup 1.0000x reference)
#include <cuda_runtime.h>
#include <math_constants.h>
#include <cstdio>

// ---------------------------------------------------------------------------
// Problem constants
// ---------------------------------------------------------------------------
#define S_LEN 2048
#define DIM   2048
#define NH    32
#define NKVH  8
#define HD    64
#define QDIM  (NH*HD)    // 2048
#define KVDIM (NKVH*HD)  // 512

// ---------------------------------------------------------------------------
// Scratch (no allocation allowed -> __device__ globals)
// ---------------------------------------------------------------------------
__device__ float g_Q [S_LEN * QDIM];   // 16 MB
__device__ float g_K [S_LEN * KVDIM];  //  4 MB
__device__ float g_V [S_LEN * KVDIM];  //  4 MB
__device__ float g_AO[S_LEN * QDIM];   // 16 MB

// ---------------------------------------------------------------------------
// NT GEMM with bias:  C[M,N] = A[M,K] * B[N,K]^T + bias[N]
// A row-major (lda=K), B row-major (ldb=K), C row-major (ldc=N).
// BM=BN=128, BK=8, 256 threads, 8x8 per-thread microtile, reg prefetch.
// ---------------------------------------------------------------------------
__global__ __launch_bounds__(256)
void gemm_nt_bias(const float* __restrict__ A, const float* __restrict__ B,
                  const float* __restrict__ bias, float* __restrict__ C,
                  int Kdim, int lda, int ldb, int ldc)
{
    __shared__ float As[8][128];
    __shared__ float Bs[8][128];

    const int tid  = threadIdx.x;
    const int tx   = tid & 15;      // 0..15 -> 8 cols each
    const int ty   = tid >> 4;      // 0..15 -> 8 rows each
    const int row0 = blockIdx.y * 128;
    const int col0 = blockIdx.x * 128;

    const int lrow = tid >> 1;          // 0..127
    const int lseg = (tid & 1) * 4;     // 0 or 4

    const float* Aptr = A + (size_t)(row0 + lrow) * lda + lseg;
    const float* Bptr = B + (size_t)(col0 + lrow) * ldb + lseg;

    float acc[8][8];
    #pragma unroll
    for (int i = 0; i < 8; ++i)
        #pragma unroll
        for (int j = 0; j < 8; ++j) acc[i][j] = 0.f;

    float4 a4 = *(const float4*)(Aptr);
    float4 b4 = *(const float4*)(Bptr);

    for (int k0 = 0; k0 < Kdim; k0 += 8) {
        As[lseg+0][lrow] = a4.x; As[lseg+1][lrow] = a4.y;
        As[lseg+2][lrow] = a4.z; As[lseg+3][lrow] = a4.w;
        Bs[lseg+0][lrow] = b4.x; Bs[lseg+1][lrow] = b4.y;
        Bs[lseg+2][lrow] = b4.z; Bs[lseg+3][lrow] = b4.w;
        __syncthreads();

        if (k0 + 8 < Kdim) {              // prefetch next k-tile into registers
            a4 = *(const float4*)(Aptr + k0 + 8);
            b4 = *(const float4*)(Bptr + k0 + 8);
        }

        #pragma unroll
        for (int k = 0; k < 8; ++k) {
            float4 a0 = *(const float4*)&As[k][ty*8];
            float4 a1 = *(const float4*)&As[k][ty*8+4];
            float4 bb0 = *(const float4*)&Bs[k][tx*8];
            float4 bb1 = *(const float4*)&Bs[k][tx*8+4];
            float ar[8] = {a0.x,a0.y,a0.z,a0.w,a1.x,a1.y,a1.z,a1.w};
            float br[8] = {bb0.x,bb0.y,bb0.z,bb0.w,bb1.x,bb1.y,bb1.z,bb1.w};
            #pragma unroll
            for (int i = 0; i < 8; ++i)
                #pragma unroll
                for (int j = 0; j < 8; ++j)
                    acc[i][j] = fmaf(ar[i], br[j], acc[i][j]);
        }
        __syncthreads();
    }

    #pragma unroll
    for (int i = 0; i < 8; ++i) {
        const int r = row0 + ty*8 + i;
        #pragma unroll
        for (int j = 0; j < 8; j += 4) {
            const int c = col0 + tx*8 + j;
            float4 o;
            o.x = acc[i][j+0] + bias[c+0];
            o.y = acc[i][j+1] + bias[c+1];
            o.z = acc[i][j+2] + bias[c+2];
            o.w = acc[i][j+3] + bias[c+3];
            *(float4*)&C[(size_t)r * ldc + c] = o;
        }
    }
}

// ---------------------------------------------------------------------------
// RoPE (in-place). rope_cache row s: [cos(0..63) | sin(0..63)], cos[d]==cos[d+32].
// One thread per (s, head, d<32) pair.
// ---------------------------------------------------------------------------
__global__ void rope_kernel(float* __restrict__ T, const float* __restrict__ rope,
                            int nheads, int ld)
{
    int idx = blockIdx.x * blockDim.x + threadIdx.x;
    int d  = idx & 31;
    int sh = idx >> 5;
    int h  = sh % nheads;
    int s  = sh / nheads;
    if (s >= S_LEN) return;
    float c  = rope[s*128 + d];
    float sn = rope[s*128 + 64 + d];
    float* p = T + (size_t)s * ld + h*HD + d;
    float x0 = p[0], x1 = p[32];
    p[0]  = fmaf(x0, c, -x1*sn);
    p[32] = fmaf(x1, c,  x0*sn);
}

// ---------------------------------------------------------------------------
// Flash attention, causal, GQA (REP=4), sink-LSE renorm.
// 64x64 tiles, 256 threads (16x16), 4x4 per-thread microtiles.
// Smem: Qs[d][r], KPs = Ks[d][c] (GEMM1) overlaid with P^T[k][r] (GEMM2),
//       Vs[k][c]. 3 * 16KB = 48KB static.
// Softmax row reductions over 16-lane half-warp groups via shfl.xor.
// ---------------------------------------------------------------------------
__global__ __launch_bounds__(256)
void attn_kernel(const float* __restrict__ Q, const float* __restrict__ K,
                 const float* __restrict__ V, const float* __restrict__ sinks,
                 float* __restrict__ O)
{
    __shared__ float Qs [64*64];
    __shared__ float KPs[64*64];
    __shared__ float Vs [64*64];

    const int h   = blockIdx.y;
    const int qi  = (int)gridDim.x - 1 - (int)blockIdx.x;  // heavy blocks first
    const int s0  = qi * 64;
    const int kvh = h >> 2;                                // REP = 4
    const int tid = threadIdx.x;
    const int tx  = tid & 15;
    const int ty  = tid >> 4;

    // --- load Q tile transposed: Qs[d*64 + r] ---
    {
        const int r    = tid >> 2;          // 0..63
        const int dseg = (tid & 3) * 16;    // 0,16,32,48
        const float* qp = Q + (size_t)(s0 + r) * QDIM + h*HD + dseg;
        #pragma unroll
        for (int t = 0; t < 4; ++t) {
            float4 v = *(const float4*)(qp + t*4);
            int d = dseg + t*4;
            Qs[(d+0)*64 + r] = v.x; Qs[(d+1)*64 + r] = v.y;
            Qs[(d+2)*64 + r] = v.z; Qs[(d+3)*64 + r] = v.w;
        }
    }

    float m_i[4], l_i[4];
    float acc[4][4];
    #pragma unroll
    for (int i = 0; i < 4; ++i) {
        m_i[i] = -CUDART_INF_F; l_i[i] = 0.f;
        #pragma unroll
        for (int j = 0; j < 4; ++j) acc[i][j] = 0.f;
    }

    const float scale = 0.125f;  // 1/sqrt(64)

    for (int kb = 0; kb <= qi; ++kb) {
        const int ks0 = kb * 64;
        __syncthreads();  // prev iter done reading KPs/Vs (and Qs write on iter 0)

        // --- load K tile transposed KPs[d*64+c]; V tile natural Vs[k*64+c] ---
        {
            const int c    = tid >> 2;
            const int dseg = (tid & 3) * 16;
            const float* kp = K + (size_t)(ks0 + c) * KVDIM + kvh*HD + dseg;
            const float* vp = V + (size_t)(ks0 + c) * KVDIM + kvh*HD + dseg;
            #pragma unroll
            for (int t = 0; t < 4; ++t) {
                float4 kv = *(const float4*)(kp + t*4);
                int d = dseg + t*4;
                KPs[(d+0)*64 + c] = kv.x; KPs[(d+1)*64 + c] = kv.y;
                KPs[(d+2)*64 + c] = kv.z; KPs[(d+3)*64 + c] = kv.w;
                float4 vv = *(const float4*)(vp + t*4);
                *(float4*)&Vs[c*64 + dseg + t*4] = vv;
            }
        }
        __syncthreads();

        // --- GEMM1: sc[i][j] = sum_d Qs[d][ty*4+i] * Ks[d][tx*4+j] ---
        float sc[4][4];
        #pragma unroll
        for (int i = 0; i < 4; ++i)
            #pragma unroll
            for (int j = 0; j < 4; ++j) sc[i][j] = 0.f;

        #pragma unroll 8
        for (int d = 0; d < 64; ++d) {
            float4 qv = *(const float4*)&Qs [d*64 + ty*4];
            float4 kv = *(const float4*)&KPs[d*64 + tx*4];
            float qr[4] = {qv.x,qv.y,qv.z,qv.w};
            float kr[4] = {kv.x,kv.y,kv.z,kv.w};
            #pragma unroll
            for (int i = 0; i < 4; ++i)
                #pragma unroll
                for (int j = 0; j < 4; ++j)
                    sc[i][j] = fmaf(qr[i], kr[j], sc[i][j]);
        }

        // scale + causal mask (only diagonal block needs masking)
        #pragma unroll
        for (int i = 0; i < 4; ++i)
            #pragma unroll
            for (int j = 0; j < 4; ++j) {
                sc[i][j] *= scale;
                if (kb == qi && (ks0 + tx*4 + j) > (s0 + ty*4 + i))
                    sc[i][j] = -CUDART_INF_F;
            }

        __syncthreads();  // all threads done reading Ks before P^T overwrites KPs

        // --- online softmax (row groups = 16 lanes sharing ty) + write P^T ---
        #pragma unroll
        for (int i = 0; i < 4; ++i) {
            float mx = fmaxf(fmaxf(sc[i][0], sc[i][1]), fmaxf(sc[i][2], sc[i][3]));
            #pragma unroll
            for (int off = 8; off >= 1; off >>= 1)
                mx = fmaxf(mx, __shfl_xor_sync(0xffffffffu, mx, off));
            float mnew = fmaxf(m_i[i], mx);
            float corr = __expf(m_i[i] - mnew);   // exp(-inf)=0 on first iter

            float p[4], ps = 0.f;
            #pragma unroll
            for (int j = 0; j < 4; ++j) {
                p[j] = __expf(sc[i][j] - mnew);   // masked entries -> 0
                ps += p[j];
            }
            #pragma unroll
            for (int off = 8; off >= 1; off >>= 1)
                ps += __shfl_xor_sync(0xffffffffu, ps, off);

            l_i[i] = l_i[i] * corr + ps;
            m_i[i] = mnew;
            #pragma unroll
            for (int j = 0; j < 4; ++j) {
                acc[i][j] *= corr;
                KPs[(tx*4 + j)*64 + (ty*4 + i)] = p[j];   // P^T[k][r]
            }
        }
        __syncthreads();

        // --- GEMM2: acc[i][j] += sum_k P^T[k][ty*4+i] * Vs[k][tx*4+j] ---
        #pragma unroll 8
        for (int k = 0; k < 64; ++k) {
            float4 pv = *(const float4*)&KPs[k*64 + ty*4];
            float4 vv = *(const float4*)&Vs [k*64 + tx*4];
            float pr[4] = {pv.x,pv.y,pv.z,pv.w};
            float vr[4] = {vv.x,vv.y,vv.z,vv.w};
            #pragma unroll
            for (int i = 0; i < 4; ++i)
                #pragma unroll
                for (int j = 0; j < 4; ++j)
                    acc[i][j] = fmaf(pr[i], vr[j], acc[i][j]);
        }
    }

    // --- epilogue: 1/l, sink-LSE renorm, store ---
    const float sink = sinks[h];
    #pragma unroll
    for (int i = 0; i < 4; ++i) {
        float lse  = m_i[i] + __logf(l_i[i]);
        float comb = fmaxf(lse, sink) + log1pf(__expf(-fabsf(lse - sink)));
        float ren  = __expf(fmaxf(lse - comb, -20.f));   // upper clip 0 implicit
        float inv  = ren / l_i[i];
        const int r = s0 + ty*4 + i;
        float4 o;
        o.x = acc[i][0]*inv; o.y = acc[i][1]*inv;
        o.z = acc[i][2]*inv; o.w = acc[i][3]*inv;
        *(float4*)&O[(size_t)r * QDIM + h*HD + tx*4] = o;
    }
}

// ---------------------------------------------------------------------------
// Launch
// ---------------------------------------------------------------------------
extern "C" void kernel_launch(void* const* d_in, const int* in_sizes, int n_in,
                              void* d_out, int out_size)
{
    const float* x     = (const float*)d_in[0];
    const float* rope  = (const float*)d_in[1];
    const float* wq_w  = (const float*)d_in[2];
    const float* wq_b  = (const float*)d_in[3];
    const float* wk_w  = (const float*)d_in[4];
    const float* wk_b  = (const float*)d_in[5];
    const float* wv_w  = (const float*)d_in[6];
    const float* wv_b  = (const float*)d_in[7];
    const float* wo_w  = (const float*)d_in[8];
    const float* wo_b  = (const float*)d_in[9];
    const float* sinks = (const float*)d_in[10];
    float* out = (float*)d_out;

    float *Q, *Kb, *Vb, *AO;
    cudaGetSymbolAddress((void**)&Q,  g_Q);
    cudaGetSymbolAddress((void**)&Kb, g_K);
    cudaGetSymbolAddress((void**)&Vb, g_V);
    cudaGetSymbolAddress((void**)&AO, g_AO);

    // QKV projections
    gemm_nt_bias<<<dim3(QDIM/128,  S_LEN/128), 256>>>(x, wq_w, wq_b, Q,  DIM, DIM, DIM, QDIM);
    gemm_nt_bias<<<dim3(KVDIM/128, S_LEN/128), 256>>>(x, wk_w, wk_b, Kb, DIM, DIM, DIM, KVDIM);
    gemm_nt_bias<<<dim3(KVDIM/128, S_LEN/128), 256>>>(x, wv_w, wv_b, Vb, DIM, DIM, DIM, KVDIM);

    // RoPE in place
    rope_kernel<<<(S_LEN*NH  *32)/256, 256>>>(Q,  rope, NH,   QDIM);
    rope_kernel<<<(S_LEN*NKVH*32)/256, 256>>>(Kb, rope, NKVH, KVDIM);

    // Attention
    attn_kernel<<<dim3(S_LEN/64, NH), 256>>>(Q, Kb, Vb, sinks, AO);

    // Output projection
    gemm_nt_bias<<<dim3(DIM/128, S_LEN/128), 256>>>(AO, wo_w, wo_b, out, QDIM, QDIM, QDIM, DIM);
}

// round 2
// speedup vs baseline: 1.3104x; 1.3104x over previous
#include <cuda_runtime.h>
#include <math_constants.h>
#include <cstdint>

// ---------------------------------------------------------------------------
// Problem constants
// ---------------------------------------------------------------------------
#define S_LEN 2048
#define DIM   2048
#define NH    32
#define NKVH  8
#define HD    64
#define QDIM  (NH*HD)    // 2048
#define KVDIM (NKVH*HD)  // 512

// ---------------------------------------------------------------------------
// Scratch
// ---------------------------------------------------------------------------
__device__ float g_Q [S_LEN * QDIM];
__device__ float g_K [S_LEN * KVDIM];
__device__ float g_V [S_LEN * KVDIM];
__device__ float g_AO[S_LEN * QDIM];

// ---------------------------------------------------------------------------
// tf32 helpers
// ---------------------------------------------------------------------------
__device__ __forceinline__ void mma_tf32(float c[4],
    uint32_t a0, uint32_t a1, uint32_t a2, uint32_t a3,
    uint32_t b0, uint32_t b1)
{
    asm volatile(
        "mma.sync.aligned.m16n8k8.row.col.f32.tf32.tf32.f32 "
        "{%0,%1,%2,%3}, {%4,%5,%6,%7}, {%8,%9}, {%0,%1,%2,%3};"
        : "+f"(c[0]), "+f"(c[1]), "+f"(c[2]), "+f"(c[3])
        : "r"(a0), "r"(a1), "r"(a2), "r"(a3), "r"(b0), "r"(b1));
}

__device__ __forceinline__ void split_tf32(float x, uint32_t& hi, uint32_t& lo)
{
    uint32_t h = __float_as_uint(x) & 0xffffe000u;   // exact tf32-representable head
    hi = h;
    lo = __float_as_uint(x - __uint_as_float(h));    // exact residual
}

__device__ __forceinline__ void cp_async16(uint32_t dst, const float* src)
{
    asm volatile("cp.async.cg.shared.global [%0], [%1], 16;\n" :: "r"(dst), "l"(src));
}

// ---------------------------------------------------------------------------
// 3xTF32 NT GEMM with bias:  C[M,N] = A[M,K] * B[N,K]^T + bias[N]
// BM=BN=128, BK=16, 256 threads (8 warps, 2x4), warp tile 64x32.
// Smem [m][k] layout, pad stride 20 -> conflict-free m16n8k8 fragment loads.
// cp.async double buffering.
// ---------------------------------------------------------------------------
#define BM 128
#define BN 128
#define BK 16
#define PAD 20

__global__ __launch_bounds__(256)
void gemm_tf32_nt_bias(const float* __restrict__ A, const float* __restrict__ B,
                       const float* __restrict__ bias, float* __restrict__ C,
                       int Kdim, int lda, int ldb, int ldc)
{
    __shared__ float As[2][BM * PAD];
    __shared__ float Bs[2][BN * PAD];

    const int tid  = threadIdx.x;
    const int wid  = tid >> 5;
    const int lane = tid & 31;
    const int g    = lane >> 2;     // 0..7
    const int t    = lane & 3;      // 0..3
    const int wm   = (wid & 1) * 64;
    const int wn   = (wid >> 1) * 32;
    const int row0 = blockIdx.y * BM;
    const int col0 = blockIdx.x * BN;

    // loader mapping: thread covers rows lm0 and lm0+64, k-quad lkq
    const int lm0 = tid >> 2;          // 0..63
    const int lkq = (tid & 3) * 4;     // 0,4,8,12

    const float* Aload = A + (size_t)(row0 + lm0) * lda + lkq;
    const float* Bload = B + (size_t)(col0 + lm0) * ldb + lkq;

    const uint32_t sA = (uint32_t)__cvta_generic_to_shared(&As[0][0]);
    const uint32_t sB = (uint32_t)__cvta_generic_to_shared(&Bs[0][0]);
    const uint32_t dOffA = (uint32_t)(lm0 * PAD + lkq) * 4u;
    const uint32_t half  = (uint32_t)(64 * PAD) * 4u;   // +64 rows in bytes
    const uint32_t bufBytes = (uint32_t)(BM * PAD) * 4u;

    float acc[4][4][4];
    #pragma unroll
    for (int mt = 0; mt < 4; ++mt)
        #pragma unroll
        for (int nt = 0; nt < 4; ++nt)
            #pragma unroll
            for (int e = 0; e < 4; ++e) acc[mt][nt][e] = 0.f;

    const int T = Kdim / BK;

    // prologue: tile 0 -> buf 0
    {
        cp_async16(sA + dOffA,        Aload);
        cp_async16(sA + dOffA + half, Aload + (size_t)64 * lda);
        cp_async16(sB + dOffA,        Bload);
        cp_async16(sB + dOffA + half, Bload + (size_t)64 * ldb);
        asm volatile("cp.async.commit_group;\n");
    }

    for (int tt = 0; tt < T; ++tt) {
        const int cur = tt & 1;
        if (tt + 1 < T) {
            const int nxt = cur ^ 1;
            const float* Ap = Aload + (tt + 1) * BK;
            const float* Bp = Bload + (tt + 1) * BK;
            const uint32_t off = (uint32_t)nxt * bufBytes + dOffA;
            cp_async16(sA + off,        Ap);
            cp_async16(sA + off + half, Ap + (size_t)64 * lda);
            cp_async16(sB + off,        Bp);
            cp_async16(sB + off + half, Bp + (size_t)64 * ldb);
            asm volatile("cp.async.commit_group;\n");
            asm volatile("cp.async.wait_group 1;\n");
        } else {
            asm volatile("cp.async.wait_group 0;\n");
        }
        __syncthreads();

        const float* Ab = &As[cur][0];
        const float* Bb = &Bs[cur][0];

        #pragma unroll
        for (int kk = 0; kk < BK; kk += 8) {
            uint32_t ah[4][4], al[4][4];
            #pragma unroll
            for (int mt = 0; mt < 4; ++mt) {
                const int rb = wm + mt * 16 + g;
                float a0 = Ab[rb       * PAD + kk + t];
                float a1 = Ab[(rb + 8) * PAD + kk + t];
                float a2 = Ab[rb       * PAD + kk + t + 4];
                float a3 = Ab[(rb + 8) * PAD + kk + t + 4];
                split_tf32(a0, ah[mt][0], al[mt][0]);
                split_tf32(a1, ah[mt][1], al[mt][1]);
                split_tf32(a2, ah[mt][2], al[mt][2]);
                split_tf32(a3, ah[mt][3], al[mt][3]);
            }
            uint32_t bh[4][2], bl[4][2];
            #pragma unroll
            for (int nt = 0; nt < 4; ++nt) {
                const int cb = wn + nt * 8 + g;
                float b0 = Bb[cb * PAD + kk + t];
                float b1 = Bb[cb * PAD + kk + t + 4];
                split_tf32(b0, bh[nt][0], bl[nt][0]);
                split_tf32(b1, bh[nt][1], bl[nt][1]);
            }
            // pass 1: hi*hi
            #pragma unroll
            for (int mt = 0; mt < 4; ++mt)
                #pragma unroll
                for (int nt = 0; nt < 4; ++nt)
                    mma_tf32(acc[mt][nt], ah[mt][0], ah[mt][1], ah[mt][2], ah[mt][3],
                             bh[nt][0], bh[nt][1]);
            // pass 2: hi*lo
            #pragma unroll
            for (int mt = 0; mt < 4; ++mt)
                #pragma unroll
                for (int nt = 0; nt < 4; ++nt)
                    mma_tf32(acc[mt][nt], ah[mt][0], ah[mt][1], ah[mt][2], ah[mt][3],
                             bl[nt][0], bl[nt][1]);
            // pass 3: lo*hi
            #pragma unroll
            for (int mt = 0; mt < 4; ++mt)
                #pragma unroll
                for (int nt = 0; nt < 4; ++nt)
                    mma_tf32(acc[mt][nt], al[mt][0], al[mt][1], al[mt][2], al[mt][3],
                             bh[nt][0], bh[nt][1]);
        }
        __syncthreads();
    }

    // epilogue
    #pragma unroll
    for (int mt = 0; mt < 4; ++mt) {
        const int r = row0 + wm + mt * 16 + g;
        #pragma unroll
        for (int nt = 0; nt < 4; ++nt) {
            const int c = col0 + wn + nt * 8 + 2 * t;
            float2 o0, o1;
            o0.x = acc[mt][nt][0] + bias[c];
            o0.y = acc[mt][nt][1] + bias[c + 1];
            o1.x = acc[mt][nt][2] + bias[c];
            o1.y = acc[mt][nt][3] + bias[c + 1];
            *(float2*)&C[(size_t)r       * ldc + c] = o0;
            *(float2*)&C[(size_t)(r + 8) * ldc + c] = o1;
        }
    }
}

// ---------------------------------------------------------------------------
// RoPE (in-place), unchanged from R1
// ---------------------------------------------------------------------------
__global__ void rope_kernel(float* __restrict__ T, const float* __restrict__ rope,
                            int nheads, int ld)
{
    int idx = blockIdx.x * blockDim.x + threadIdx.x;
    int d  = idx & 31;
    int sh = idx >> 5;
    int h  = sh % nheads;
    int s  = sh / nheads;
    if (s >= S_LEN) return;
    float c  = rope[s*128 + d];
    float sn = rope[s*128 + 64 + d];
    float* p = T + (size_t)s * ld + h*HD + d;
    float x0 = p[0], x1 = p[32];
    p[0]  = fmaf(x0, c, -x1*sn);
    p[32] = fmaf(x1, c,  x0*sn);
}

// ---------------------------------------------------------------------------
// Flash attention (fp32 scalar), unchanged from R1
// ---------------------------------------------------------------------------
__global__ __launch_bounds__(256)
void attn_kernel(const float* __restrict__ Q, const float* __restrict__ K,
                 const float* __restrict__ V, const float* __restrict__ sinks,
                 float* __restrict__ O)
{
    __shared__ float Qs [64*64];
    __shared__ float KPs[64*64];
    __shared__ float Vs [64*64];

    const int h   = blockIdx.y;
    const int qi  = (int)gridDim.x - 1 - (int)blockIdx.x;
    const int s0  = qi * 64;
    const int kvh = h >> 2;
    const int tid = threadIdx.x;
    const int tx  = tid & 15;
    const int ty  = tid >> 4;

    {
        const int r    = tid >> 2;
        const int dseg = (tid & 3) * 16;
        const float* qp = Q + (size_t)(s0 + r) * QDIM + h*HD + dseg;
        #pragma unroll
        for (int t = 0; t < 4; ++t) {
            float4 v = *(const float4*)(qp + t*4);
            int d = dseg + t*4;
            Qs[(d+0)*64 + r] = v.x; Qs[(d+1)*64 + r] = v.y;
            Qs[(d+2)*64 + r] = v.z; Qs[(d+3)*64 + r] = v.w;
        }
    }

    float m_i[4], l_i[4];
    float acc[4][4];
    #pragma unroll
    for (int i = 0; i < 4; ++i) {
        m_i[i] = -CUDART_INF_F; l_i[i] = 0.f;
        #pragma unroll
        for (int j = 0; j < 4; ++j) acc[i][j] = 0.f;
    }

    const float scale = 0.125f;

    for (int kb = 0; kb <= qi; ++kb) {
        const int ks0 = kb * 64;
        __syncthreads();

        {
            const int c    = tid >> 2;
            const int dseg = (tid & 3) * 16;
            const float* kp = K + (size_t)(ks0 + c) * KVDIM + kvh*HD + dseg;
            const float* vp = V + (size_t)(ks0 + c) * KVDIM + kvh*HD + dseg;
            #pragma unroll
            for (int t = 0; t < 4; ++t) {
                float4 kv = *(const float4*)(kp + t*4);
                int d = dseg + t*4;
                KPs[(d+0)*64 + c] = kv.x; KPs[(d+1)*64 + c] = kv.y;
                KPs[(d+2)*64 + c] = kv.z; KPs[(d+3)*64 + c] = kv.w;
                float4 vv = *(const float4*)(vp + t*4);
                *(float4*)&Vs[c*64 + dseg + t*4] = vv;
            }
        }
        __syncthreads();

        float sc[4][4];
        #pragma unroll
        for (int i = 0; i < 4; ++i)
            #pragma unroll
            for (int j = 0; j < 4; ++j) sc[i][j] = 0.f;

        #pragma unroll 8
        for (int d = 0; d < 64; ++d) {
            float4 qv = *(const float4*)&Qs [d*64 + ty*4];
            float4 kv = *(const float4*)&KPs[d*64 + tx*4];
            float qr[4] = {qv.x,qv.y,qv.z,qv.w};
            float kr[4] = {kv.x,kv.y,kv.z,kv.w};
            #pragma unroll
            for (int i = 0; i < 4; ++i)
                #pragma unroll
                for (int j = 0; j < 4; ++j)
                    sc[i][j] = fmaf(qr[i], kr[j], sc[i][j]);
        }

        #pragma unroll
        for (int i = 0; i < 4; ++i)
            #pragma unroll
            for (int j = 0; j < 4; ++j) {
                sc[i][j] *= scale;
                if (kb == qi && (ks0 + tx*4 + j) > (s0 + ty*4 + i))
                    sc[i][j] = -CUDART_INF_F;
            }

        __syncthreads();

        #pragma unroll
        for (int i = 0; i < 4; ++i) {
            float mx = fmaxf(fmaxf(sc[i][0], sc[i][1]), fmaxf(sc[i][2], sc[i][3]));
            #pragma unroll
            for (int off = 8; off >= 1; off >>= 1)
                mx = fmaxf(mx, __shfl_xor_sync(0xffffffffu, mx, off));
            float mnew = fmaxf(m_i[i], mx);
            float corr = __expf(m_i[i] - mnew);

            float p[4], ps = 0.f;
            #pragma unroll
            for (int j = 0; j < 4; ++j) {
                p[j] = __expf(sc[i][j] - mnew);
                ps += p[j];
            }
            #pragma unroll
            for (int off = 8; off >= 1; off >>= 1)
                ps += __shfl_xor_sync(0xffffffffu, ps, off);

            l_i[i] = l_i[i] * corr + ps;
            m_i[i] = mnew;
            #pragma unroll
            for (int j = 0; j < 4; ++j) {
                acc[i][j] *= corr;
                KPs[(tx*4 + j)*64 + (ty*4 + i)] = p[j];
            }
        }
        __syncthreads();

        #pragma unroll 8
        for (int k = 0; k < 64; ++k) {
            float4 pv = *(const float4*)&KPs[k*64 + ty*4];
            float4 vv = *(const float4*)&Vs [k*64 + tx*4];
            float pr[4] = {pv.x,pv.y,pv.z,pv.w};
            float vr[4] = {vv.x,vv.y,vv.z,vv.w};
            #pragma unroll
            for (int i = 0; i < 4; ++i)
                #pragma unroll
                for (int j = 0; j < 4; ++j)
                    acc[i][j] = fmaf(pr[i], vr[j], acc[i][j]);
        }
    }

    const float sink = sinks[h];
    #pragma unroll
    for (int i = 0; i < 4; ++i) {
        float lse  = m_i[i] + __logf(l_i[i]);
        float comb = fmaxf(lse, sink) + log1pf(__expf(-fabsf(lse - sink)));
        float ren  = __expf(fmaxf(lse - comb, -20.f));
        float inv  = ren / l_i[i];
        const int r = s0 + ty*4 + i;
        float4 o;
        o.x = acc[i][0]*inv; o.y = acc[i][1]*inv;
        o.z = acc[i][2]*inv; o.w = acc[i][3]*inv;
        *(float4*)&O[(size_t)r * QDIM + h*HD + tx*4] = o;
    }
}

// ---------------------------------------------------------------------------
// Launch
// ---------------------------------------------------------------------------
extern "C" void kernel_launch(void* const* d_in, const int* in_sizes, int n_in,
                              void* d_out, int out_size)
{
    const float* x     = (const float*)d_in[0];
    const float* rope  = (const float*)d_in[1];
    const float* wq_w  = (const float*)d_in[2];
    const float* wq_b  = (const float*)d_in[3];
    const float* wk_w  = (const float*)d_in[4];
    const float* wk_b  = (const float*)d_in[5];
    const float* wv_w  = (const float*)d_in[6];
    const float* wv_b  = (const float*)d_in[7];
    const float* wo_w  = (const float*)d_in[8];
    const float* wo_b  = (const float*)d_in[9];
    const float* sinks = (const float*)d_in[10];
    float* out = (float*)d_out;

    float *Q, *Kb, *Vb, *AO;
    cudaGetSymbolAddress((void**)&Q,  g_Q);
    cudaGetSymbolAddress((void**)&Kb, g_K);
    cudaGetSymbolAddress((void**)&Vb, g_V);
    cudaGetSymbolAddress((void**)&AO, g_AO);

    gemm_tf32_nt_bias<<<dim3(QDIM/BN,  S_LEN/BM), 256>>>(x, wq_w, wq_b, Q,  DIM, DIM, DIM, QDIM);
    gemm_tf32_nt_bias<<<dim3(KVDIM/BN, S_LEN/BM), 256>>>(x, wk_w, wk_b, Kb, DIM, DIM, DIM, KVDIM);
    gemm_tf32_nt_bias<<<dim3(KVDIM/BN, S_LEN/BM), 256>>>(x, wv_w, wv_b, Vb, DIM, DIM, DIM, KVDIM);

    rope_kernel<<<(S_LEN*NH  *32)/256, 256>>>(Q,  rope, NH,   QDIM);
    rope_kernel<<<(S_LEN*NKVH*32)/256, 256>>>(Kb, rope, NKVH, KVDIM);

    attn_kernel<<<dim3(S_LEN/64, NH), 256>>>(Q, Kb, Vb, sinks, AO);

    gemm_tf32_nt_bias<<<dim3(DIM/BN, S_LEN/BM), 256>>>(AO, wo_w, wo_b, out, QDIM, QDIM, QDIM, DIM);
}

// round 3
// speedup vs baseline: 1.6962x; 1.2944x over previous
#include <cuda_runtime.h>
#include <math_constants.h>
#include <cstdint>

// ---------------------------------------------------------------------------
// Problem constants
// ---------------------------------------------------------------------------
#define S_LEN 2048
#define DIM   2048
#define NH    32
#define NKVH  8
#define HD    64
#define QDIM  (NH*HD)    // 2048
#define KVDIM (NKVH*HD)  // 512

// ---------------------------------------------------------------------------
// Scratch
// ---------------------------------------------------------------------------
__device__ float g_Q [S_LEN * QDIM];
__device__ float g_K [S_LEN * KVDIM];
__device__ float g_V [S_LEN * KVDIM];
__device__ float g_AO[S_LEN * QDIM];

// ---------------------------------------------------------------------------
// tf32 helpers
// ---------------------------------------------------------------------------
__device__ __forceinline__ void mma_tf32(float c[4],
    uint32_t a0, uint32_t a1, uint32_t a2, uint32_t a3,
    uint32_t b0, uint32_t b1)
{
    asm volatile(
        "mma.sync.aligned.m16n8k8.row.col.f32.tf32.tf32.f32 "
        "{%0,%1,%2,%3}, {%4,%5,%6,%7}, {%8,%9}, {%0,%1,%2,%3};"
        : "+f"(c[0]), "+f"(c[1]), "+f"(c[2]), "+f"(c[3])
        : "r"(a0), "r"(a1), "r"(a2), "r"(a3), "r"(b0), "r"(b1));
}

__device__ __forceinline__ void split_tf32(float x, uint32_t& hi, uint32_t& lo)
{
    uint32_t h = __float_as_uint(x) & 0xffffe000u;
    hi = h;
    lo = __float_as_uint(x - __uint_as_float(h));
}

__device__ __forceinline__ void split_tf32f(float x, float& hi, float& lo)
{
    hi = __uint_as_float(__float_as_uint(x) & 0xffffe000u);
    lo = x - hi;
}

__device__ __forceinline__ void cp_async16(uint32_t dst, const float* src)
{
    asm volatile("cp.async.cg.shared.global [%0], [%1], 16;\n" :: "r"(dst), "l"(src));
}

// ---------------------------------------------------------------------------
// 3xTF32 NT GEMM with bias (unchanged from R2)
// ---------------------------------------------------------------------------
#define BM 128
#define BN 128
#define BK 16
#define PAD 20

__global__ __launch_bounds__(256)
void gemm_tf32_nt_bias(const float* __restrict__ A, const float* __restrict__ B,
                       const float* __restrict__ bias, float* __restrict__ C,
                       int Kdim, int lda, int ldb, int ldc)
{
    __shared__ float As[2][BM * PAD];
    __shared__ float Bs[2][BN * PAD];

    const int tid  = threadIdx.x;
    const int wid  = tid >> 5;
    const int lane = tid & 31;
    const int g    = lane >> 2;
    const int t    = lane & 3;
    const int wm   = (wid & 1) * 64;
    const int wn   = (wid >> 1) * 32;
    const int row0 = blockIdx.y * BM;
    const int col0 = blockIdx.x * BN;

    const int lm0 = tid >> 2;
    const int lkq = (tid & 3) * 4;

    const float* Aload = A + (size_t)(row0 + lm0) * lda + lkq;
    const float* Bload = B + (size_t)(col0 + lm0) * ldb + lkq;

    const uint32_t sA = (uint32_t)__cvta_generic_to_shared(&As[0][0]);
    const uint32_t sB = (uint32_t)__cvta_generic_to_shared(&Bs[0][0]);
    const uint32_t dOffA = (uint32_t)(lm0 * PAD + lkq) * 4u;
    const uint32_t half  = (uint32_t)(64 * PAD) * 4u;
    const uint32_t bufBytes = (uint32_t)(BM * PAD) * 4u;

    float acc[4][4][4];
    #pragma unroll
    for (int mt = 0; mt < 4; ++mt)
        #pragma unroll
        for (int nt = 0; nt < 4; ++nt)
            #pragma unroll
            for (int e = 0; e < 4; ++e) acc[mt][nt][e] = 0.f;

    const int T = Kdim / BK;

    {
        cp_async16(sA + dOffA,        Aload);
        cp_async16(sA + dOffA + half, Aload + (size_t)64 * lda);
        cp_async16(sB + dOffA,        Bload);
        cp_async16(sB + dOffA + half, Bload + (size_t)64 * ldb);
        asm volatile("cp.async.commit_group;\n");
    }

    for (int tt = 0; tt < T; ++tt) {
        const int cur = tt & 1;
        if (tt + 1 < T) {
            const int nxt = cur ^ 1;
            const float* Ap = Aload + (tt + 1) * BK;
            const float* Bp = Bload + (tt + 1) * BK;
            const uint32_t off = (uint32_t)nxt * bufBytes + dOffA;
            cp_async16(sA + off,        Ap);
            cp_async16(sA + off + half, Ap + (size_t)64 * lda);
            cp_async16(sB + off,        Bp);
            cp_async16(sB + off + half, Bp + (size_t)64 * ldb);
            asm volatile("cp.async.commit_group;\n");
            asm volatile("cp.async.wait_group 1;\n");
        } else {
            asm volatile("cp.async.wait_group 0;\n");
        }
        __syncthreads();

        const float* Ab = &As[cur][0];
        const float* Bb = &Bs[cur][0];

        #pragma unroll
        for (int kk = 0; kk < BK; kk += 8) {
            uint32_t ah[4][4], al[4][4];
            #pragma unroll
            for (int mt = 0; mt < 4; ++mt) {
                const int rb = wm + mt * 16 + g;
                float a0 = Ab[rb       * PAD + kk + t];
                float a1 = Ab[(rb + 8) * PAD + kk + t];
                float a2 = Ab[rb       * PAD + kk + t + 4];
                float a3 = Ab[(rb + 8) * PAD + kk + t + 4];
                split_tf32(a0, ah[mt][0], al[mt][0]);
                split_tf32(a1, ah[mt][1], al[mt][1]);
                split_tf32(a2, ah[mt][2], al[mt][2]);
                split_tf32(a3, ah[mt][3], al[mt][3]);
            }
            uint32_t bh[4][2], bl[4][2];
            #pragma unroll
            for (int nt = 0; nt < 4; ++nt) {
                const int cb = wn + nt * 8 + g;
                float b0 = Bb[cb * PAD + kk + t];
                float b1 = Bb[cb * PAD + kk + t + 4];
                split_tf32(b0, bh[nt][0], bl[nt][0]);
                split_tf32(b1, bh[nt][1], bl[nt][1]);
            }
            #pragma unroll
            for (int mt = 0; mt < 4; ++mt)
                #pragma unroll
                for (int nt = 0; nt < 4; ++nt)
                    mma_tf32(acc[mt][nt], ah[mt][0], ah[mt][1], ah[mt][2], ah[mt][3],
                             bh[nt][0], bh[nt][1]);
            #pragma unroll
            for (int mt = 0; mt < 4; ++mt)
                #pragma unroll
                for (int nt = 0; nt < 4; ++nt)
                    mma_tf32(acc[mt][nt], ah[mt][0], ah[mt][1], ah[mt][2], ah[mt][3],
                             bl[nt][0], bl[nt][1]);
            #pragma unroll
            for (int mt = 0; mt < 4; ++mt)
                #pragma unroll
                for (int nt = 0; nt < 4; ++nt)
                    mma_tf32(acc[mt][nt], al[mt][0], al[mt][1], al[mt][2], al[mt][3],
                             bh[nt][0], bh[nt][1]);
        }
        __syncthreads();
    }

    #pragma unroll
    for (int mt = 0; mt < 4; ++mt) {
        const int r = row0 + wm + mt * 16 + g;
        #pragma unroll
        for (int nt = 0; nt < 4; ++nt) {
            const int c = col0 + wn + nt * 8 + 2 * t;
            float2 o0, o1;
            o0.x = acc[mt][nt][0] + bias[c];
            o0.y = acc[mt][nt][1] + bias[c + 1];
            o1.x = acc[mt][nt][2] + bias[c];
            o1.y = acc[mt][nt][3] + bias[c + 1];
            *(float2*)&C[(size_t)r       * ldc + c] = o0;
            *(float2*)&C[(size_t)(r + 8) * ldc + c] = o1;
        }
    }
}

// ---------------------------------------------------------------------------
// RoPE (in-place)
// ---------------------------------------------------------------------------
__global__ void rope_kernel(float* __restrict__ T, const float* __restrict__ rope,
                            int nheads, int ld)
{
    int idx = blockIdx.x * blockDim.x + threadIdx.x;
    int d  = idx & 31;
    int sh = idx >> 5;
    int h  = sh % nheads;
    int s  = sh / nheads;
    if (s >= S_LEN) return;
    float c  = rope[s*128 + d];
    float sn = rope[s*128 + 64 + d];
    float* p = T + (size_t)s * ld + h*HD + d;
    float x0 = p[0], x1 = p[32];
    p[0]  = fmaf(x0, c, -x1*sn);
    p[32] = fmaf(x1, c,  x0*sn);
}

// ---------------------------------------------------------------------------
// Tensor-core flash attention (3xTF32), causal, GQA, sink renorm.
// Block: 128 q-rows x 1 head, 8 warps (16 q-rows each), KV tiles of 64.
// Dynamic smem: K/V pre-split hi/lo planes, ld=68 (conflict-free frags).
// ---------------------------------------------------------------------------
#define ALD 68
#define PLANE (64*ALD)   // 4352 floats

__global__ __launch_bounds__(256)
void attn_tc_kernel(const float* __restrict__ Q, const float* __restrict__ K,
                    const float* __restrict__ V, const float* __restrict__ sinks,
                    float* __restrict__ O)
{
    extern __shared__ float dyn[];
    float* KH = dyn;
    float* KL = dyn + PLANE;
    float* VH = dyn + 2*PLANE;
    float* VL = dyn + 3*PLANE;

    const int h    = blockIdx.y;
    const int qi   = (int)gridDim.x - 1 - (int)blockIdx.x;
    const int s0   = qi * 128;
    const int kvh  = h >> 2;
    const int tid  = threadIdx.x;
    const int w    = tid >> 5;
    const int lane = tid & 31;
    const int g    = lane >> 2;
    const int t    = lane & 3;
    const int wrow = w * 16;      // warp's first q row (block-local)

    // ---- stage Q tile into dyn (overlaying KH/KL), then build register frags
    {
        const int r  = tid >> 1;             // 0..127
        const int c0 = (tid & 1) * 32;
        const float* qp = Q + (size_t)(s0 + r) * QDIM + h*HD + c0;
        #pragma unroll
        for (int i = 0; i < 8; ++i) {
            float4 v = *(const float4*)(qp + 4*i);
            *(float4*)&dyn[r*ALD + c0 + 4*i] = v;
        }
    }
    __syncthreads();

    uint32_t qh[8][4], ql[8][4];
    #pragma unroll
    for (int kt = 0; kt < 8; ++kt) {
        float q0 = dyn[(wrow + g    )*ALD + kt*8 + t    ];
        float q1 = dyn[(wrow + g + 8)*ALD + kt*8 + t    ];
        float q2 = dyn[(wrow + g    )*ALD + kt*8 + t + 4];
        float q3 = dyn[(wrow + g + 8)*ALD + kt*8 + t + 4];
        split_tf32(q0, qh[kt][0], ql[kt][0]);
        split_tf32(q1, qh[kt][1], ql[kt][1]);
        split_tf32(q2, qh[kt][2], ql[kt][2]);
        split_tf32(q3, qh[kt][3], ql[kt][3]);
    }
    __syncthreads();   // Q staging reads done before K/V planes overwrite

    // ---- state ----
    float m0 = -CUDART_INF_F, m1 = -CUDART_INF_F;
    float l0 = 0.f, l1 = 0.f;
    float o[8][4];
    #pragma unroll
    for (int nt = 0; nt < 8; ++nt)
        #pragma unroll
        for (int e = 0; e < 4; ++e) o[nt][e] = 0.f;

    const float scale = 0.125f;
    const int kb_end = 2*qi + 2;   // number of KV tiles

    for (int kb = 0; kb < kb_end; ++kb) {
        const int ks0 = kb * 64;

        // ---- cooperative load + split K,V into hi/lo planes ----
        {
            const int r   = tid >> 2;           // 0..63
            const int c0l = (tid & 3) * 16;
            const float* kp = K + (size_t)(ks0 + r) * KVDIM + kvh*HD + c0l;
            const float* vp = V + (size_t)(ks0 + r) * KVDIM + kvh*HD + c0l;
            #pragma unroll
            for (int i = 0; i < 4; ++i) {
                float4 kv = *(const float4*)(kp + 4*i);
                float4 hi4, lo4;
                split_tf32f(kv.x, hi4.x, lo4.x);
                split_tf32f(kv.y, hi4.y, lo4.y);
                split_tf32f(kv.z, hi4.z, lo4.z);
                split_tf32f(kv.w, hi4.w, lo4.w);
                *(float4*)&KH[r*ALD + c0l + 4*i] = hi4;
                *(float4*)&KL[r*ALD + c0l + 4*i] = lo4;
                float4 vv = *(const float4*)(vp + 4*i);
                split_tf32f(vv.x, hi4.x, lo4.x);
                split_tf32f(vv.y, hi4.y, lo4.y);
                split_tf32f(vv.z, hi4.z, lo4.z);
                split_tf32f(vv.w, hi4.w, lo4.w);
                *(float4*)&VH[r*ALD + c0l + 4*i] = hi4;
                *(float4*)&VL[r*ALD + c0l + 4*i] = lo4;
            }
        }
        __syncthreads();

        // fully-masked warp tile? (all cols > all rows)
        const bool skip = (ks0 > s0 + wrow + 15);
        if (!skip) {
            // ---- S = Q K^T (warp tile 16x64) ----
            float s[8][4];
            #pragma unroll
            for (int nt = 0; nt < 8; ++nt)
                #pragma unroll
                for (int e = 0; e < 4; ++e) s[nt][e] = 0.f;

            #pragma unroll
            for (int kt = 0; kt < 8; ++kt) {
                #pragma unroll
                for (int nt = 0; nt < 8; ++nt) {
                    uint32_t bh0 = __float_as_uint(KH[(nt*8 + g)*ALD + kt*8 + t    ]);
                    uint32_t bh1 = __float_as_uint(KH[(nt*8 + g)*ALD + kt*8 + t + 4]);
                    uint32_t bl0 = __float_as_uint(KL[(nt*8 + g)*ALD + kt*8 + t    ]);
                    uint32_t bl1 = __float_as_uint(KL[(nt*8 + g)*ALD + kt*8 + t + 4]);
                    mma_tf32(s[nt], qh[kt][0], qh[kt][1], qh[kt][2], qh[kt][3], bh0, bh1);
                    mma_tf32(s[nt], qh[kt][0], qh[kt][1], qh[kt][2], qh[kt][3], bl0, bl1);
                    mma_tf32(s[nt], ql[kt][0], ql[kt][1], ql[kt][2], ql[kt][3], bh0, bh1);
                }
            }

            // ---- scale + causal mask ----
            const bool need_mask = (ks0 + 63 > s0 + wrow);
            const int row0g = s0 + wrow + g;
            #pragma unroll
            for (int nt = 0; nt < 8; ++nt) {
                #pragma unroll
                for (int e = 0; e < 4; ++e) s[nt][e] *= scale;
                if (need_mask) {
                    const int c = ks0 + nt*8 + 2*t;
                    if (c     > row0g    ) s[nt][0] = -CUDART_INF_F;
                    if (c + 1 > row0g    ) s[nt][1] = -CUDART_INF_F;
                    if (c     > row0g + 8) s[nt][2] = -CUDART_INF_F;
                    if (c + 1 > row0g + 8) s[nt][3] = -CUDART_INF_F;
                }
            }

            // ---- online softmax (rows g and g+8, reduce over t-quad) ----
            float mx0 = -CUDART_INF_F, mx1 = -CUDART_INF_F;
            #pragma unroll
            for (int nt = 0; nt < 8; ++nt) {
                mx0 = fmaxf(mx0, fmaxf(s[nt][0], s[nt][1]));
                mx1 = fmaxf(mx1, fmaxf(s[nt][2], s[nt][3]));
            }
            mx0 = fmaxf(mx0, __shfl_xor_sync(0xffffffffu, mx0, 1));
            mx0 = fmaxf(mx0, __shfl_xor_sync(0xffffffffu, mx0, 2));
            mx1 = fmaxf(mx1, __shfl_xor_sync(0xffffffffu, mx1, 1));
            mx1 = fmaxf(mx1, __shfl_xor_sync(0xffffffffu, mx1, 2));

            float mn0 = fmaxf(m0, mx0), mn1 = fmaxf(m1, mx1);
            float corr0 = __expf(m0 - mn0), corr1 = __expf(m1 - mn1);

            float ps0 = 0.f, ps1 = 0.f;
            #pragma unroll
            for (int nt = 0; nt < 8; ++nt) {
                s[nt][0] = __expf(s[nt][0] - mn0);
                s[nt][1] = __expf(s[nt][1] - mn0);
                s[nt][2] = __expf(s[nt][2] - mn1);
                s[nt][3] = __expf(s[nt][3] - mn1);
                ps0 += s[nt][0] + s[nt][1];
                ps1 += s[nt][2] + s[nt][3];
            }
            ps0 += __shfl_xor_sync(0xffffffffu, ps0, 1);
            ps0 += __shfl_xor_sync(0xffffffffu, ps0, 2);
            ps1 += __shfl_xor_sync(0xffffffffu, ps1, 1);
            ps1 += __shfl_xor_sync(0xffffffffu, ps1, 2);

            l0 = l0 * corr0 + ps0;  m0 = mn0;
            l1 = l1 * corr1 + ps1;  m1 = mn1;

            #pragma unroll
            for (int nt = 0; nt < 8; ++nt) {
                o[nt][0] *= corr0; o[nt][1] *= corr0;
                o[nt][2] *= corr1; o[nt][3] *= corr1;
            }

            // ---- PV: convert P (C-frag) -> A-frag via shuffles, then MMA ----
            const int lq = lane & ~3;
            const int l0s = lq | (t >> 1);
            const int l2s = l0s + 2;
            const bool podd = (t & 1);

            #pragma unroll
            for (int kt = 0; kt < 8; ++kt) {
                float v0 = __shfl_sync(0xffffffffu, s[kt][0], l0s);
                float v1 = __shfl_sync(0xffffffffu, s[kt][1], l0s);
                float v2 = __shfl_sync(0xffffffffu, s[kt][2], l0s);
                float v3 = __shfl_sync(0xffffffffu, s[kt][3], l0s);
                float u0 = __shfl_sync(0xffffffffu, s[kt][0], l2s);
                float u1 = __shfl_sync(0xffffffffu, s[kt][1], l2s);
                float u2 = __shfl_sync(0xffffffffu, s[kt][2], l2s);
                float u3 = __shfl_sync(0xffffffffu, s[kt][3], l2s);
                float a0f = podd ? v1 : v0;   // P(g,   kt*8+t)
                float a1f = podd ? v3 : v2;   // P(g+8, kt*8+t)
                float a2f = podd ? u1 : u0;   // P(g,   kt*8+t+4)
                float a3f = podd ? u3 : u2;   // P(g+8, kt*8+t+4)

                uint32_t ah0, al0, ah1, al1, ah2, al2, ah3, al3;
                split_tf32(a0f, ah0, al0);
                split_tf32(a1f, ah1, al1);
                split_tf32(a2f, ah2, al2);
                split_tf32(a3f, ah3, al3);

                #pragma unroll
                for (int nt = 0; nt < 8; ++nt) {
                    uint32_t bh0 = __float_as_uint(VH[(kt*8 + t    )*ALD + nt*8 + g]);
                    uint32_t bh1 = __float_as_uint(VH[(kt*8 + t + 4)*ALD + nt*8 + g]);
                    uint32_t bl0 = __float_as_uint(VL[(kt*8 + t    )*ALD + nt*8 + g]);
                    uint32_t bl1 = __float_as_uint(VL[(kt*8 + t + 4)*ALD + nt*8 + g]);
                    mma_tf32(o[nt], ah0, ah1, ah2, ah3, bh0, bh1);
                    mma_tf32(o[nt], ah0, ah1, ah2, ah3, bl0, bl1);
                    mma_tf32(o[nt], al0, al1, al2, al3, bh0, bh1);
                }
            }
        }
        __syncthreads();   // compute done before next tile overwrites planes
    }

    // ---- epilogue: sink-LSE renorm + store ----
    const float sink = sinks[h];
    float lse0 = m0 + __logf(l0);
    float lse1 = m1 + __logf(l1);
    float cb0 = fmaxf(lse0, sink) + log1pf(__expf(-fabsf(lse0 - sink)));
    float cb1 = fmaxf(lse1, sink) + log1pf(__expf(-fabsf(lse1 - sink)));
    float inv0 = __expf(fmaxf(lse0 - cb0, -20.f)) / l0;
    float inv1 = __expf(fmaxf(lse1 - cb1, -20.f)) / l1;

    const int r0 = s0 + wrow + g;
    #pragma unroll
    for (int nt = 0; nt < 8; ++nt) {
        const int c = h*HD + nt*8 + 2*t;
        float2 w0, w1;
        w0.x = o[nt][0] * inv0; w0.y = o[nt][1] * inv0;
        w1.x = o[nt][2] * inv1; w1.y = o[nt][3] * inv1;
        *(float2*)&O[(size_t)r0       * QDIM + c] = w0;
        *(float2*)&O[(size_t)(r0 + 8) * QDIM + c] = w1;
    }
}

// ---------------------------------------------------------------------------
// Launch
// ---------------------------------------------------------------------------
extern "C" void kernel_launch(void* const* d_in, const int* in_sizes, int n_in,
                              void* d_out, int out_size)
{
    const float* x     = (const float*)d_in[0];
    const float* rope  = (const float*)d_in[1];
    const float* wq_w  = (const float*)d_in[2];
    const float* wq_b  = (const float*)d_in[3];
    const float* wk_w  = (const float*)d_in[4];
    const float* wk_b  = (const float*)d_in[5];
    const float* wv_w  = (const float*)d_in[6];
    const float* wv_b  = (const float*)d_in[7];
    const float* wo_w  = (const float*)d_in[8];
    const float* wo_b  = (const float*)d_in[9];
    const float* sinks = (const float*)d_in[10];
    float* out = (float*)d_out;

    float *Q, *Kb, *Vb, *AO;
    cudaGetSymbolAddress((void**)&Q,  g_Q);
    cudaGetSymbolAddress((void**)&Kb, g_K);
    cudaGetSymbolAddress((void**)&Vb, g_V);
    cudaGetSymbolAddress((void**)&AO, g_AO);

    gemm_tf32_nt_bias<<<dim3(QDIM/BN,  S_LEN/BM), 256>>>(x, wq_w, wq_b, Q,  DIM, DIM, DIM, QDIM);
    gemm_tf32_nt_bias<<<dim3(KVDIM/BN, S_LEN/BM), 256>>>(x, wk_w, wk_b, Kb, DIM, DIM, DIM, KVDIM);
    gemm_tf32_nt_bias<<<dim3(KVDIM/BN, S_LEN/BM), 256>>>(x, wv_w, wv_b, Vb, DIM, DIM, DIM, KVDIM);

    rope_kernel<<<(S_LEN*NH  *32)/256, 256>>>(Q,  rope, NH,   QDIM);
    rope_kernel<<<(S_LEN*NKVH*32)/256, 256>>>(Kb, rope, NKVH, KVDIM);

    const int attn_smem = 4 * PLANE * (int)sizeof(float);   // 69632 B
    cudaFuncSetAttribute(attn_tc_kernel, cudaFuncAttributeMaxDynamicSharedMemorySize, attn_smem);
    attn_tc_kernel<<<dim3(S_LEN/128, NH), 256, attn_smem>>>(Q, Kb, Vb, sinks, AO);

    gemm_tf32_nt_bias<<<dim3(DIM/BN, S_LEN/BM), 256>>>(AO, wo_w, wo_b, out, QDIM, QDIM, QDIM, DIM);
}

// round 6
// speedup vs baseline: 1.8881x; 1.1132x over previous
#include <cuda_runtime.h>
#include <cuda_bf16.h>
#include <math_constants.h>
#include <cstdint>

// ---------------------------------------------------------------------------
// Problem constants
// ---------------------------------------------------------------------------
#define S_LEN 2048
#define DIM   2048
#define NH    32
#define NKVH  8
#define HD    64
#define QDIM  (NH*HD)    // 2048
#define KVDIM (NKVH*HD)  // 512

// ---------------------------------------------------------------------------
// Scratch
// ---------------------------------------------------------------------------
__device__ float g_Q [S_LEN * QDIM];
__device__ float g_K [S_LEN * KVDIM];
__device__ float g_V [S_LEN * KVDIM];
__device__ float g_AO[S_LEN * QDIM];

// ---------------------------------------------------------------------------
// bf16 split helpers
// ---------------------------------------------------------------------------
// pack hi(a),hi(b) into bf16x2 (a in low half); return residuals
__device__ __forceinline__ uint32_t bfsplit2(float a, float b, float& ra, float& rb)
{
    __nv_bfloat16 ha = __float2bfloat16_rn(a);
    __nv_bfloat16 hb = __float2bfloat16_rn(b);
    ra = a - __bfloat162float(ha);
    rb = b - __bfloat162float(hb);
    return ((uint32_t)__bfloat16_as_ushort(hb) << 16) | (uint32_t)__bfloat16_as_ushort(ha);
}
__device__ __forceinline__ uint32_t bfpack2(float a, float b)
{
    __nv_bfloat16 ha = __float2bfloat16_rn(a);
    __nv_bfloat16 hb = __float2bfloat16_rn(b);
    return ((uint32_t)__bfloat16_as_ushort(hb) << 16) | (uint32_t)__bfloat16_as_ushort(ha);
}

// m16n8k16 bf16 MMA, fp32 accumulate
__device__ __forceinline__ void mma_bf16(float c[4],
    uint32_t a0, uint32_t a1, uint32_t a2, uint32_t a3,
    uint32_t b0, uint32_t b1)
{
    asm volatile(
        "mma.sync.aligned.m16n8k16.row.col.f32.bf16.bf16.f32 "
        "{%0,%1,%2,%3}, {%4,%5,%6,%7}, {%8,%9}, {%0,%1,%2,%3};"
        : "+f"(c[0]), "+f"(c[1]), "+f"(c[2]), "+f"(c[3])
        : "r"(a0), "r"(a1), "r"(a2), "r"(a3), "r"(b0), "r"(b1));
}

__device__ __forceinline__ void cp_async16(uint32_t dst, const float* src)
{
    asm volatile("cp.async.cg.shared.global [%0], [%1], 16;\n" :: "r"(dst), "l"(src));
}

// ---------------------------------------------------------------------------
// bf16x3 NT GEMM with bias:  C[M,N] = A[M,K] * B[N,K]^T + bias[N]
// BM=BN=128, BK=16, 256 threads (8 warps 2x4), warp tile 64x32.
// ---------------------------------------------------------------------------
#define BM 128
#define BN 128
#define BK 16
#define PAD 20

__global__ __launch_bounds__(256)
void gemm_bf16x3_nt_bias(const float* __restrict__ A, const float* __restrict__ B,
                         const float* __restrict__ bias, float* __restrict__ C,
                         int Kdim, int lda, int ldb, int ldc)
{
    __shared__ float As[2][BM * PAD];
    __shared__ float Bs[2][BN * PAD];

    const int tid  = threadIdx.x;
    const int wid  = tid >> 5;
    const int lane = tid & 31;
    const int g    = lane >> 2;
    const int t    = lane & 3;
    const int wm   = (wid & 1) * 64;
    const int wn   = (wid >> 1) * 32;
    const int row0 = blockIdx.y * BM;
    const int col0 = blockIdx.x * BN;

    const int lm0 = tid >> 2;
    const int lkq = (tid & 3) * 4;

    const float* Aload = A + (size_t)(row0 + lm0) * lda + lkq;
    const float* Bload = B + (size_t)(col0 + lm0) * ldb + lkq;

    const uint32_t sA = (uint32_t)__cvta_generic_to_shared(&As[0][0]);
    const uint32_t sB = (uint32_t)__cvta_generic_to_shared(&Bs[0][0]);
    const uint32_t dOffA = (uint32_t)(lm0 * PAD + lkq) * 4u;
    const uint32_t half  = (uint32_t)(64 * PAD) * 4u;
    const uint32_t bufBytes = (uint32_t)(BM * PAD) * 4u;

    float acc[4][4][4];
    #pragma unroll
    for (int mt = 0; mt < 4; ++mt)
        #pragma unroll
        for (int nt = 0; nt < 4; ++nt)
            #pragma unroll
            for (int e = 0; e < 4; ++e) acc[mt][nt][e] = 0.f;

    const int T = Kdim / BK;

    {
        cp_async16(sA + dOffA,        Aload);
        cp_async16(sA + dOffA + half, Aload + (size_t)64 * lda);
        cp_async16(sB + dOffA,        Bload);
        cp_async16(sB + dOffA + half, Bload + (size_t)64 * ldb);
        asm volatile("cp.async.commit_group;\n");
    }

    for (int tt = 0; tt < T; ++tt) {
        const int cur = tt & 1;
        if (tt + 1 < T) {
            const int nxt = cur ^ 1;
            const float* Ap = Aload + (tt + 1) * BK;
            const float* Bp = Bload + (tt + 1) * BK;
            const uint32_t off = (uint32_t)nxt * bufBytes + dOffA;
            cp_async16(sA + off,        Ap);
            cp_async16(sA + off + half, Ap + (size_t)64 * lda);
            cp_async16(sB + off,        Bp);
            cp_async16(sB + off + half, Bp + (size_t)64 * ldb);
            asm volatile("cp.async.commit_group;\n");
            asm volatile("cp.async.wait_group 1;\n");
        } else {
            asm volatile("cp.async.wait_group 0;\n");
        }
        __syncthreads();

        const float* Ab = &As[cur][0];
        const float* Bb = &Bs[cur][0];

        // fragments for the whole k16 tile
        uint32_t ah[4][4], al[4][4];
        #pragma unroll
        for (int mt = 0; mt < 4; ++mt) {
            const int rb = wm + mt * 16 + g;
            float2 p0 = *(const float2*)&Ab[rb       * PAD + 2*t];
            float2 p1 = *(const float2*)&Ab[(rb + 8) * PAD + 2*t];
            float2 p2 = *(const float2*)&Ab[rb       * PAD + 2*t + 8];
            float2 p3 = *(const float2*)&Ab[(rb + 8) * PAD + 2*t + 8];
            float r0, r1;
            ah[mt][0] = bfsplit2(p0.x, p0.y, r0, r1); al[mt][0] = bfpack2(r0, r1);
            ah[mt][1] = bfsplit2(p1.x, p1.y, r0, r1); al[mt][1] = bfpack2(r0, r1);
            ah[mt][2] = bfsplit2(p2.x, p2.y, r0, r1); al[mt][2] = bfpack2(r0, r1);
            ah[mt][3] = bfsplit2(p3.x, p3.y, r0, r1); al[mt][3] = bfpack2(r0, r1);
        }
        uint32_t bh[4][2], bl[4][2];
        #pragma unroll
        for (int nt = 0; nt < 4; ++nt) {
            const int cb = wn + nt * 8 + g;
            float2 q0 = *(const float2*)&Bb[cb * PAD + 2*t];
            float2 q1 = *(const float2*)&Bb[cb * PAD + 2*t + 8];
            float r0, r1;
            bh[nt][0] = bfsplit2(q0.x, q0.y, r0, r1); bl[nt][0] = bfpack2(r0, r1);
            bh[nt][1] = bfsplit2(q1.x, q1.y, r0, r1); bl[nt][1] = bfpack2(r0, r1);
        }

        #pragma unroll
        for (int mt = 0; mt < 4; ++mt)
            #pragma unroll
            for (int nt = 0; nt < 4; ++nt)
                mma_bf16(acc[mt][nt], ah[mt][0], ah[mt][1], ah[mt][2], ah[mt][3],
                         bh[nt][0], bh[nt][1]);
        #pragma unroll
        for (int mt = 0; mt < 4; ++mt)
            #pragma unroll
            for (int nt = 0; nt < 4; ++nt)
                mma_bf16(acc[mt][nt], ah[mt][0], ah[mt][1], ah[mt][2], ah[mt][3],
                         bl[nt][0], bl[nt][1]);
        #pragma unroll
        for (int mt = 0; mt < 4; ++mt)
            #pragma unroll
            for (int nt = 0; nt < 4; ++nt)
                mma_bf16(acc[mt][nt], al[mt][0], al[mt][1], al[mt][2], al[mt][3],
                         bh[nt][0], bh[nt][1]);
        __syncthreads();
    }

    #pragma unroll
    for (int mt = 0; mt < 4; ++mt) {
        const int r = row0 + wm + mt * 16 + g;
        #pragma unroll
        for (int nt = 0; nt < 4; ++nt) {
            const int c = col0 + wn + nt * 8 + 2 * t;
            float2 o0, o1;
            o0.x = acc[mt][nt][0] + bias[c];
            o0.y = acc[mt][nt][1] + bias[c + 1];
            o1.x = acc[mt][nt][2] + bias[c];
            o1.y = acc[mt][nt][3] + bias[c + 1];
            *(float2*)&C[(size_t)r       * ldc + c] = o0;
            *(float2*)&C[(size_t)(r + 8) * ldc + c] = o1;
        }
    }
}

// ---------------------------------------------------------------------------
// RoPE (in-place)
// ---------------------------------------------------------------------------
__global__ void rope_kernel(float* __restrict__ T, const float* __restrict__ rope,
                            int nheads, int ld)
{
    int idx = blockIdx.x * blockDim.x + threadIdx.x;
    int d  = idx & 31;
    int sh = idx >> 5;
    int h  = sh % nheads;
    int s  = sh / nheads;
    if (s >= S_LEN) return;
    float c  = rope[s*128 + d];
    float sn = rope[s*128 + 64 + d];
    float* p = T + (size_t)s * ld + h*HD + d;
    float x0 = p[0], x1 = p[32];
    p[0]  = fmaf(x0, c, -x1*sn);
    p[32] = fmaf(x1, c,  x0*sn);
}

// ---------------------------------------------------------------------------
// bf16x3 flash attention (m16n8k16), causal, GQA, sink renorm.
// Block: 128 q-rows x 1 head, 8 warps (16 q-rows each), KV tiles of 64.
// K/V stored as packed bf16x2 hi/lo planes, stride 35 words.
// ---------------------------------------------------------------------------
#define ALD  68                 // fp32 Q staging stride (words)
#define KSTR 35                 // packed plane stride (uint32 words)
#define PLW  (64*KSTR)          // words per plane
#define ATTN_SMEM (4*PLW*4 > 128*ALD*4 ? 4*PLW*4 : 128*ALD*4)

__global__ __launch_bounds__(256)
void attn_bf16_kernel(const float* __restrict__ Q, const float* __restrict__ K,
                      const float* __restrict__ V, const float* __restrict__ sinks,
                      float* __restrict__ O)
{
    extern __shared__ float dyn[];
    uint32_t* dynu = (uint32_t*)dyn;
    uint32_t* KHp = dynu;
    uint32_t* KLp = dynu + PLW;
    uint32_t* VHp = dynu + 2*PLW;
    uint32_t* VLp = dynu + 3*PLW;

    const int h    = blockIdx.y;
    const int qi   = (int)gridDim.x - 1 - (int)blockIdx.x;
    const int s0   = qi * 128;
    const int kvh  = h >> 2;
    const int tid  = threadIdx.x;
    const int w    = tid >> 5;
    const int lane = tid & 31;
    const int g    = lane >> 2;
    const int t    = lane & 3;
    const int wrow = w * 16;

    // ---- stage Q (fp32) into dyn, then build bf16 hi/lo A-fragments ----
    {
        const int r  = tid >> 1;
        const int c0 = (tid & 1) * 32;
        const float* qp = Q + (size_t)(s0 + r) * QDIM + h*HD + c0;
        #pragma unroll
        for (int i = 0; i < 8; ++i) {
            float4 v = *(const float4*)(qp + 4*i);
            *(float4*)&dyn[r*ALD + c0 + 4*i] = v;
        }
    }
    __syncthreads();

    uint32_t qh[4][4], ql[4][4];
    #pragma unroll
    for (int kt = 0; kt < 4; ++kt) {
        float2 p0 = *(const float2*)&dyn[(wrow + g    )*ALD + kt*16 + 2*t];
        float2 p1 = *(const float2*)&dyn[(wrow + g + 8)*ALD + kt*16 + 2*t];
        float2 p2 = *(const float2*)&dyn[(wrow + g    )*ALD + kt*16 + 2*t + 8];
        float2 p3 = *(const float2*)&dyn[(wrow + g + 8)*ALD + kt*16 + 2*t + 8];
        float r0, r1;
        qh[kt][0] = bfsplit2(p0.x, p0.y, r0, r1); ql[kt][0] = bfpack2(r0, r1);
        qh[kt][1] = bfsplit2(p1.x, p1.y, r0, r1); ql[kt][1] = bfpack2(r0, r1);
        qh[kt][2] = bfsplit2(p2.x, p2.y, r0, r1); ql[kt][2] = bfpack2(r0, r1);
        qh[kt][3] = bfsplit2(p3.x, p3.y, r0, r1); ql[kt][3] = bfpack2(r0, r1);
    }
    __syncthreads();

    float m0 = -CUDART_INF_F, m1 = -CUDART_INF_F;
    float l0 = 0.f, l1 = 0.f;
    float o[8][4];
    #pragma unroll
    for (int nt = 0; nt < 8; ++nt)
        #pragma unroll
        for (int e = 0; e < 4; ++e) o[nt][e] = 0.f;

    const float scale = 0.125f;
    const int kb_end = 2*qi + 2;

    for (int kb = 0; kb < kb_end; ++kb) {
        const int ks0 = kb * 64;

        // ---- K loader: 64 rows x 64 hd -> packed pairs along hd ----
        {
            const int r   = tid >> 2;            // 0..63 (seq)
            const int cs  = (tid & 3) * 16;      // hd segment
            const float* kp = K + (size_t)(ks0 + r) * KVDIM + kvh*HD + cs;
            float f[16];
            *(float4*)&f[0]  = *(const float4*)(kp);
            *(float4*)&f[4]  = *(const float4*)(kp + 4);
            *(float4*)&f[8]  = *(const float4*)(kp + 8);
            *(float4*)&f[12] = *(const float4*)(kp + 12);
            const int base = r*KSTR + cs/2;
            #pragma unroll
            for (int j = 0; j < 8; ++j) {
                float r0, r1;
                KHp[base + j] = bfsplit2(f[2*j], f[2*j+1], r0, r1);
                KLp[base + j] = bfpack2(r0, r1);
            }
        }
        // ---- V loader: packed pairs along seq (transposed) ----
        {
            const int sp = tid >> 3;             // 0..31 (seq pair)
            const int cs = (tid & 7) * 8;        // hd segment
            const float* vp0 = V + (size_t)(ks0 + 2*sp) * KVDIM + kvh*HD + cs;
            const float* vp1 = vp0 + KVDIM;
            float a[8], b[8];
            *(float4*)&a[0] = *(const float4*)(vp0);
            *(float4*)&a[4] = *(const float4*)(vp0 + 4);
            *(float4*)&b[0] = *(const float4*)(vp1);
            *(float4*)&b[4] = *(const float4*)(vp1 + 4);
            #pragma unroll
            for (int c = 0; c < 8; ++c) {
                float r0, r1;
                VHp[(cs + c)*KSTR + sp] = bfsplit2(a[c], b[c], r0, r1);
                VLp[(cs + c)*KSTR + sp] = bfpack2(r0, r1);
            }
        }
        __syncthreads();

        const bool skip = (ks0 > s0 + wrow + 15);
        if (!skip) {
            // ---- S = Q K^T ----
            float s[8][4];
            #pragma unroll
            for (int nt = 0; nt < 8; ++nt)
                #pragma unroll
                for (int e = 0; e < 4; ++e) s[nt][e] = 0.f;

            #pragma unroll
            for (int kt = 0; kt < 4; ++kt) {
                #pragma unroll
                for (int nt = 0; nt < 8; ++nt) {
                    const int nb = (nt*8 + g)*KSTR + kt*8 + t;
                    uint32_t bh0 = KHp[nb];
                    uint32_t bh1 = KHp[nb + 4];
                    uint32_t bl0 = KLp[nb];
                    uint32_t bl1 = KLp[nb + 4];
                    mma_bf16(s[nt], qh[kt][0], qh[kt][1], qh[kt][2], qh[kt][3], bh0, bh1);
                    mma_bf16(s[nt], qh[kt][0], qh[kt][1], qh[kt][2], qh[kt][3], bl0, bl1);
                    mma_bf16(s[nt], ql[kt][0], ql[kt][1], ql[kt][2], ql[kt][3], bh0, bh1);
                }
            }

            // ---- scale + causal mask ----
            const bool need_mask = (ks0 + 63 > s0 + wrow);
            const int row0g = s0 + wrow + g;
            #pragma unroll
            for (int nt = 0; nt < 8; ++nt) {
                #pragma unroll
                for (int e = 0; e < 4; ++e) s[nt][e] *= scale;
                if (need_mask) {
                    const int c = ks0 + nt*8 + 2*t;
                    if (c     > row0g    ) s[nt][0] = -CUDART_INF_F;
                    if (c + 1 > row0g    ) s[nt][1] = -CUDART_INF_F;
                    if (c     > row0g + 8) s[nt][2] = -CUDART_INF_F;
                    if (c + 1 > row0g + 8) s[nt][3] = -CUDART_INF_F;
                }
            }

            // ---- online softmax ----
            float mx0 = -CUDART_INF_F, mx1 = -CUDART_INF_F;
            #pragma unroll
            for (int nt = 0; nt < 8; ++nt) {
                mx0 = fmaxf(mx0, fmaxf(s[nt][0], s[nt][1]));
                mx1 = fmaxf(mx1, fmaxf(s[nt][2], s[nt][3]));
            }
            mx0 = fmaxf(mx0, __shfl_xor_sync(0xffffffffu, mx0, 1));
            mx0 = fmaxf(mx0, __shfl_xor_sync(0xffffffffu, mx0, 2));
            mx1 = fmaxf(mx1, __shfl_xor_sync(0xffffffffu, mx1, 1));
            mx1 = fmaxf(mx1, __shfl_xor_sync(0xffffffffu, mx1, 2));

            float mn0 = fmaxf(m0, mx0), mn1 = fmaxf(m1, mx1);
            float corr0 = __expf(m0 - mn0), corr1 = __expf(m1 - mn1);

            float ps0 = 0.f, ps1 = 0.f;
            #pragma unroll
            for (int nt = 0; nt < 8; ++nt) {
                s[nt][0] = __expf(s[nt][0] - mn0);
                s[nt][1] = __expf(s[nt][1] - mn0);
                s[nt][2] = __expf(s[nt][2] - mn1);
                s[nt][3] = __expf(s[nt][3] - mn1);
                ps0 += s[nt][0] + s[nt][1];
                ps1 += s[nt][2] + s[nt][3];
            }
            ps0 += __shfl_xor_sync(0xffffffffu, ps0, 1);
            ps0 += __shfl_xor_sync(0xffffffffu, ps0, 2);
            ps1 += __shfl_xor_sync(0xffffffffu, ps1, 1);
            ps1 += __shfl_xor_sync(0xffffffffu, ps1, 2);

            l0 = l0 * corr0 + ps0;  m0 = mn0;
            l1 = l1 * corr1 + ps1;  m1 = mn1;

            #pragma unroll
            for (int nt = 0; nt < 8; ++nt) {
                o[nt][0] *= corr0; o[nt][1] *= corr0;
                o[nt][2] *= corr1; o[nt][3] *= corr1;
            }

            // ---- PV: P C-frag maps directly to k16 A-frag (no shuffles) ----
            #pragma unroll
            for (int kt = 0; kt < 4; ++kt) {
                float r0, r1;
                uint32_t ah0 = bfsplit2(s[2*kt  ][0], s[2*kt  ][1], r0, r1);
                uint32_t al0 = bfpack2(r0, r1);
                uint32_t ah1 = bfsplit2(s[2*kt  ][2], s[2*kt  ][3], r0, r1);
                uint32_t al1 = bfpack2(r0, r1);
                uint32_t ah2 = bfsplit2(s[2*kt+1][0], s[2*kt+1][1], r0, r1);
                uint32_t al2 = bfpack2(r0, r1);
                uint32_t ah3 = bfsplit2(s[2*kt+1][2], s[2*kt+1][3], r0, r1);
                uint32_t al3 = bfpack2(r0, r1);

                #pragma unroll
                for (int nt = 0; nt < 8; ++nt) {
                    const int nb = (nt*8 + g)*KSTR + kt*8 + t;
                    uint32_t bh0 = VHp[nb];
                    uint32_t bh1 = VHp[nb + 4];
                    uint32_t bl0 = VLp[nb];
                    uint32_t bl1 = VLp[nb + 4];
                    mma_bf16(o[nt], ah0, ah1, ah2, ah3, bh0, bh1);
                    mma_bf16(o[nt], ah0, ah1, ah2, ah3, bl0, bl1);
                    mma_bf16(o[nt], al0, al1, al2, al3, bh0, bh1);
                }
            }
        }
        __syncthreads();
    }

    // ---- epilogue: sink-LSE renorm + store ----
    const float sink = sinks[h];
    float lse0 = m0 + __logf(l0);
    float lse1 = m1 + __logf(l1);
    float cb0 = fmaxf(lse0, sink) + log1pf(__expf(-fabsf(lse0 - sink)));
    float cb1 = fmaxf(lse1, sink) + log1pf(__expf(-fabsf(lse1 - sink)));
    float inv0 = __expf(fmaxf(lse0 - cb0, -20.f)) / l0;
    float inv1 = __expf(fmaxf(lse1 - cb1, -20.f)) / l1;

    const int r0 = s0 + wrow + g;
    #pragma unroll
    for (int nt = 0; nt < 8; ++nt) {
        const int c = h*HD + nt*8 + 2*t;
        float2 w0, w1;
        w0.x = o[nt][0] * inv0; w0.y = o[nt][1] * inv0;
        w1.x = o[nt][2] * inv1; w1.y = o[nt][3] * inv1;
        *(float2*)&O[(size_t)r0       * QDIM + c] = w0;
        *(float2*)&O[(size_t)(r0 + 8) * QDIM + c] = w1;
    }
}

// ---------------------------------------------------------------------------
// Launch
// ---------------------------------------------------------------------------
extern "C" void kernel_launch(void* const* d_in, const int* in_sizes, int n_in,
                              void* d_out, int out_size)
{
    const float* x     = (const float*)d_in[0];
    const float* rope  = (const float*)d_in[1];
    const float* wq_w  = (const float*)d_in[2];
    const float* wq_b  = (const float*)d_in[3];
    const float* wk_w  = (const float*)d_in[4];
    const float* wk_b  = (const float*)d_in[5];
    const float* wv_w  = (const float*)d_in[6];
    const float* wv_b  = (const float*)d_in[7];
    const float* wo_w  = (const float*)d_in[8];
    const float* wo_b  = (const float*)d_in[9];
    const float* sinks = (const float*)d_in[10];
    float* out = (float*)d_out;

    float *Q, *Kb, *Vb, *AO;
    cudaGetSymbolAddress((void**)&Q,  g_Q);
    cudaGetSymbolAddress((void**)&Kb, g_K);
    cudaGetSymbolAddress((void**)&Vb, g_V);
    cudaGetSymbolAddress((void**)&AO, g_AO);

    gemm_bf16x3_nt_bias<<<dim3(QDIM/BN,  S_LEN/BM), 256>>>(x, wq_w, wq_b, Q,  DIM, DIM, DIM, QDIM);
    gemm_bf16x3_nt_bias<<<dim3(KVDIM/BN, S_LEN/BM), 256>>>(x, wk_w, wk_b, Kb, DIM, DIM, DIM, KVDIM);
    gemm_bf16x3_nt_bias<<<dim3(KVDIM/BN, S_LEN/BM), 256>>>(x, wv_w, wv_b, Vb, DIM, DIM, DIM, KVDIM);

    rope_kernel<<<(S_LEN*NH  *32)/256, 256>>>(Q,  rope, NH,   QDIM);
    rope_kernel<<<(S_LEN*NKVH*32)/256, 256>>>(Kb, rope, NKVH, KVDIM);

    attn_bf16_kernel<<<dim3(S_LEN/128, NH), 256, ATTN_SMEM>>>(Q, Kb, Vb, sinks, AO);

    gemm_bf16x3_nt_bias<<<dim3(DIM/BN, S_LEN/BM), 256>>>(AO, wo_w, wo_b, out, QDIM, QDIM, QDIM, DIM);
}

// round 10
// speedup vs baseline: 2.6496x; 1.4033x over previous
#include <cuda_runtime.h>
#include <cuda_bf16.h>
#include <math_constants.h>
#include <cstdint>

// ---------------------------------------------------------------------------
// Problem constants
// ---------------------------------------------------------------------------
#define S_LEN 2048
#define DIM   2048
#define NH    32
#define NKVH  8
#define HD    64
#define QDIM  2048
#define KVDIM 512

typedef unsigned short u16;

// ---------------------------------------------------------------------------
// Scratch (bf16 hi/lo planes live in global; split once, consumed many times)
// ---------------------------------------------------------------------------
__device__ __align__(16) float g_Q [S_LEN*QDIM];     // fp32 Q pre-rope
__device__ __align__(16) float g_K [S_LEN*KVDIM];    // fp32 K pre-rope
__device__ __align__(16) u16 g_Qh[S_LEN*QDIM];
__device__ __align__(16) u16 g_Ql[S_LEN*QDIM];
__device__ __align__(16) u16 g_Kh[S_LEN*KVDIM];
__device__ __align__(16) u16 g_Kl[S_LEN*KVDIM];
__device__ __align__(16) u16 g_Vth[KVDIM*S_LEN];     // V^T planes [hd][seq]
__device__ __align__(16) u16 g_Vtl[KVDIM*S_LEN];
__device__ __align__(16) u16 g_AOh[S_LEN*QDIM];
__device__ __align__(16) u16 g_AOl[S_LEN*QDIM];
__device__ __align__(16) u16 g_xh[S_LEN*DIM];
__device__ __align__(16) u16 g_xl[S_LEN*DIM];
__device__ __align__(16) u16 g_wqh[QDIM*DIM];
__device__ __align__(16) u16 g_wql[QDIM*DIM];
__device__ __align__(16) u16 g_wkh[KVDIM*DIM];
__device__ __align__(16) u16 g_wkl[KVDIM*DIM];
__device__ __align__(16) u16 g_wvh[KVDIM*DIM];
__device__ __align__(16) u16 g_wvl[KVDIM*DIM];
__device__ __align__(16) u16 g_woh[DIM*QDIM];
__device__ __align__(16) u16 g_wol[DIM*QDIM];

// ---------------------------------------------------------------------------
// Helpers
// ---------------------------------------------------------------------------
__device__ __forceinline__ u16 tobf(float x) {
    return __bfloat16_as_ushort(__float2bfloat16_rn(x));
}
__device__ __forceinline__ u16 bf_hi(float x, float& lo) {
    u16 h = tobf(x);
    lo = x - __bfloat162float(__ushort_as_bfloat16(h));
    return h;
}
__device__ __forceinline__ uint32_t bfsplit2(float a, float b, float& ra, float& rb)
{
    u16 ha = bf_hi(a, ra);
    u16 hb = bf_hi(b, rb);
    return ((uint32_t)hb << 16) | (uint32_t)ha;
}
__device__ __forceinline__ uint32_t bfpack2(float a, float b)
{
    return ((uint32_t)tobf(b) << 16) | (uint32_t)tobf(a);
}

__device__ __forceinline__ void mma_bf16(float c[4],
    uint32_t a0, uint32_t a1, uint32_t a2, uint32_t a3,
    uint32_t b0, uint32_t b1)
{
    asm volatile(
        "mma.sync.aligned.m16n8k16.row.col.f32.bf16.bf16.f32 "
        "{%0,%1,%2,%3}, {%4,%5,%6,%7}, {%8,%9}, {%0,%1,%2,%3};"
        : "+f"(c[0]), "+f"(c[1]), "+f"(c[2]), "+f"(c[3])
        : "r"(a0), "r"(a1), "r"(a2), "r"(a3), "r"(b0), "r"(b1));
}

__device__ __forceinline__ void ldsm4(uint32_t& r0, uint32_t& r1,
                                      uint32_t& r2, uint32_t& r3, uint32_t addr)
{
    asm volatile("ldmatrix.sync.aligned.m8n8.x4.shared.b16 {%0,%1,%2,%3}, [%4];"
        : "=r"(r0), "=r"(r1), "=r"(r2), "=r"(r3) : "r"(addr));
}

__device__ __forceinline__ void cp16(uint32_t dst, const void* src)
{
    asm volatile("cp.async.cg.shared.global [%0], [%1], 16;\n" :: "r"(dst), "l"(src));
}
__device__ __forceinline__ void cp_commit() {
    asm volatile("cp.async.commit_group;\n");
}
__device__ __forceinline__ void cp_wait0() {
    asm volatile("cp.async.wait_group 0;\n");
}

// ---------------------------------------------------------------------------
// split kernel: fp32 -> bf16 hi + lo planes
// ---------------------------------------------------------------------------
__global__ void split_kernel(const float* __restrict__ in, u16* __restrict__ hi,
                             u16* __restrict__ lo, int n4)
{
    int i = blockIdx.x * blockDim.x + threadIdx.x;
    if (i >= n4) return;
    float4 v = ((const float4*)in)[i];
    float l0, l1, l2, l3;
    ushort4 H, L;
    H.x = bf_hi(v.x, l0); H.y = bf_hi(v.y, l1);
    H.z = bf_hi(v.z, l2); H.w = bf_hi(v.w, l3);
    L.x = tobf(l0); L.y = tobf(l1); L.z = tobf(l2); L.w = tobf(l3);
    ((ushort4*)hi)[i] = H;
    ((ushort4*)lo)[i] = L;
}

// ---------------------------------------------------------------------------
// RoPE + split: read fp32, rotate, write bf16 hi/lo planes
// ---------------------------------------------------------------------------
__global__ void rope_split_kernel(const float* __restrict__ T, const float* __restrict__ rope,
                                  u16* __restrict__ Th, u16* __restrict__ Tl,
                                  int nheads, int ld)
{
    int idx = blockIdx.x * blockDim.x + threadIdx.x;
    int d  = idx & 31;
    int sh = idx >> 5;
    int h  = sh % nheads;
    int s  = sh / nheads;
    if (s >= S_LEN) return;
    float c  = rope[s*128 + d];
    float sn = rope[s*128 + 64 + d];
    const float* p = T + (size_t)s * ld + h*HD + d;
    float x0 = p[0], x1 = p[32];
    float y0 = fmaf(x0, c, -x1*sn);
    float y1 = fmaf(x1, c,  x0*sn);
    int b = s*ld + h*HD + d;
    float l;
    Th[b]      = bf_hi(y0, l);  Tl[b]      = tobf(l);
    Th[b + 32] = bf_hi(y1, l);  Tl[b + 32] = tobf(l);
}

// ---------------------------------------------------------------------------
// bf16x3 NT GEMM (pre-split planes):  C = A * B^T + bias
// BM=BN=128, BK=32, 256 threads (8 warps 2x4), ldmatrix fragments.
// mode 0: fp32 C;  mode 2: transposed bf16 hi/lo planes (for V).
// ---------------------------------------------------------------------------
#define GASTR 80                 // smem row stride bytes (64B data + 16 pad)
#define GPL   (128*GASTR)        // 10240 per plane
#define GBUF  (4*GPL)            // 40960 per buffer
#define GEMM_DYN (2*GBUF)        // 81920

__global__ __launch_bounds__(256)
void gemm_bf3(const u16* __restrict__ Ah, const u16* __restrict__ Al,
              const u16* __restrict__ Bh, const u16* __restrict__ Bl,
              const float* __restrict__ bias,
              float* __restrict__ C, u16* __restrict__ Ch, u16* __restrict__ Cl,
              int Kdim, int ldc, int mode)
{
    extern __shared__ char sm[];
    const uint32_t sbase = (uint32_t)__cvta_generic_to_shared(sm);

    const int tid  = threadIdx.x;
    const int wid  = tid >> 5;
    const int lane = tid & 31;
    const int g    = lane >> 2;
    const int t    = lane & 3;
    const int wm   = (wid & 1) * 64;
    const int wn   = (wid >> 1) * 32;
    const int row0 = blockIdx.y * 128;
    const int col0 = blockIdx.x * 128;

    // loader mapping: 2 threads per row, each covers 32B (2 chunks) per plane
    const int lr   = tid >> 1;
    const int half = tid & 1;
    const u16* Agh = Ah + (size_t)(row0 + lr) * Kdim + half*16;
    const u16* Agl = Al + (size_t)(row0 + lr) * Kdim + half*16;
    const u16* Bgh = Bh + (size_t)(col0 + lr) * Kdim + half*16;
    const u16* Bgl = Bl + (size_t)(col0 + lr) * Kdim + half*16;
    const uint32_t ddst = (uint32_t)(lr * GASTR + half*32);

    float acc[4][4][4];
    #pragma unroll
    for (int mt = 0; mt < 4; ++mt)
        #pragma unroll
        for (int nt = 0; nt < 4; ++nt)
            #pragma unroll
            for (int e = 0; e < 4; ++e) acc[mt][nt][e] = 0.f;

    const int T = Kdim / 32;

    // prologue
    {
        const uint32_t o = sbase + ddst;
        cp16(o,              Agh);  cp16(o + 16,            Agh + 8);
        cp16(o + GPL,        Agl);  cp16(o + GPL + 16,      Agl + 8);
        cp16(o + 2*GPL,      Bgh);  cp16(o + 2*GPL + 16,    Bgh + 8);
        cp16(o + 3*GPL,      Bgl);  cp16(o + 3*GPL + 16,    Bgl + 8);
        cp_commit();
    }

    for (int tt = 0; tt < T; ++tt) {
        const int cur = tt & 1;
        if (tt + 1 < T) {
            const int k0 = (tt + 1) * 32;
            const uint32_t o = sbase + (cur ^ 1) * GBUF + ddst;
            cp16(o,           Agh + k0);  cp16(o + 16,           Agh + k0 + 8);
            cp16(o + GPL,     Agl + k0);  cp16(o + GPL + 16,     Agl + k0 + 8);
            cp16(o + 2*GPL,   Bgh + k0);  cp16(o + 2*GPL + 16,   Bgh + k0 + 8);
            cp16(o + 3*GPL,   Bgl + k0);  cp16(o + 3*GPL + 16,   Bgl + k0 + 8);
            cp_commit();
            asm volatile("cp.async.wait_group 1;\n");
        } else {
            cp_wait0();
        }
        __syncthreads();

        const uint32_t bufA = sbase + cur * GBUF;
        const uint32_t bufB = bufA + 2*GPL;

        #pragma unroll
        for (int kk = 0; kk < 2; ++kk) {
            const uint32_t kk2 = kk * 32;   // k16 step byte offset
            uint32_t ah[4][4], al[4][4];
            #pragma unroll
            for (int mt = 0; mt < 4; ++mt) {
                uint32_t addr = bufA + (uint32_t)((wm + mt*16 + (lane & 15)) * GASTR)
                              + kk2 + ((lane >> 4) * 16);
                ldsm4(ah[mt][0], ah[mt][1], ah[mt][2], ah[mt][3], addr);
                ldsm4(al[mt][0], al[mt][1], al[mt][2], al[mt][3], addr + GPL);
            }
            uint32_t bh[4][2], bl[4][2];
            #pragma unroll
            for (int p = 0; p < 2; ++p) {
                uint32_t addr = bufB + (uint32_t)((wn + p*16 + (lane & 7) + (((lane >> 4)) << 3)) * GASTR)
                              + kk2 + (((lane >> 3) & 1) * 16);
                ldsm4(bh[2*p][0], bh[2*p][1], bh[2*p+1][0], bh[2*p+1][1], addr);
                ldsm4(bl[2*p][0], bl[2*p][1], bl[2*p+1][0], bl[2*p+1][1], addr + GPL);
            }
            #pragma unroll
            for (int mt = 0; mt < 4; ++mt)
                #pragma unroll
                for (int nt = 0; nt < 4; ++nt)
                    mma_bf16(acc[mt][nt], ah[mt][0], ah[mt][1], ah[mt][2], ah[mt][3],
                             bh[nt][0], bh[nt][1]);
            #pragma unroll
            for (int mt = 0; mt < 4; ++mt)
                #pragma unroll
                for (int nt = 0; nt < 4; ++nt)
                    mma_bf16(acc[mt][nt], ah[mt][0], ah[mt][1], ah[mt][2], ah[mt][3],
                             bl[nt][0], bl[nt][1]);
            #pragma unroll
            for (int mt = 0; mt < 4; ++mt)
                #pragma unroll
                for (int nt = 0; nt < 4; ++nt)
                    mma_bf16(acc[mt][nt], al[mt][0], al[mt][1], al[mt][2], al[mt][3],
                             bh[nt][0], bh[nt][1]);
        }
        __syncthreads();
    }

    // epilogue
    #pragma unroll
    for (int mt = 0; mt < 4; ++mt) {
        const int r = row0 + wm + mt*16 + g;
        #pragma unroll
        for (int nt = 0; nt < 4; ++nt) {
            const int c = col0 + wn + nt*8 + 2*t;
            float v00 = acc[mt][nt][0] + bias[c];
            float v01 = acc[mt][nt][1] + bias[c+1];
            float v10 = acc[mt][nt][2] + bias[c];
            float v11 = acc[mt][nt][3] + bias[c+1];
            if (mode == 0) {
                float2 o0 = {v00, v01}, o1 = {v10, v11};
                *(float2*)&C[(size_t)r       * ldc + c] = o0;
                *(float2*)&C[(size_t)(r + 8) * ldc + c] = o1;
            } else {  // mode 2: transposed bf16 planes  Vt[c][r]
                float l;
                Ch[(size_t)c     * S_LEN + r    ] = bf_hi(v00, l); Cl[(size_t)c     * S_LEN + r    ] = tobf(l);
                Ch[(size_t)(c+1) * S_LEN + r    ] = bf_hi(v01, l); Cl[(size_t)(c+1) * S_LEN + r    ] = tobf(l);
                Ch[(size_t)c     * S_LEN + r + 8] = bf_hi(v10, l); Cl[(size_t)c     * S_LEN + r + 8] = tobf(l);
                Ch[(size_t)(c+1) * S_LEN + r + 8] = bf_hi(v11, l); Cl[(size_t)(c+1) * S_LEN + r + 8] = tobf(l);
            }
        }
    }
}

// ---------------------------------------------------------------------------
// Flash attention on pre-split bf16 planes, ldmatrix fragments.
// Block: 128 q-rows x 1 head, 8 warps x 16 rows, KV tiles of 64.
// smem union: Q staging (2 planes, 128x144B) then K/V (4 planes, 64x144B).
// ---------------------------------------------------------------------------
#define QSTR 144
#define KVPL (64*QSTR)           // 9216
#define ATT_DYN (128*QSTR*2)     // 36864

__global__ __launch_bounds__(256)
void attn_kernel(const u16* __restrict__ Qh, const u16* __restrict__ Ql,
                 const u16* __restrict__ Kh, const u16* __restrict__ Kl,
                 const u16* __restrict__ Vth, const u16* __restrict__ Vtl,
                 const float* __restrict__ sinks,
                 u16* __restrict__ AOh, u16* __restrict__ AOl)
{
    extern __shared__ char sm[];
    const uint32_t sb  = (uint32_t)__cvta_generic_to_shared(sm);
    const uint32_t sKH = sb, sKL = sb + KVPL, sVH = sb + 2*KVPL, sVL = sb + 3*KVPL;

    const int h    = blockIdx.y;
    const int qi   = (int)gridDim.x - 1 - (int)blockIdx.x;
    const int s0   = qi * 128;
    const int kvh  = h >> 2;
    const int tid  = threadIdx.x;
    const int w    = tid >> 5;
    const int lane = tid & 31;
    const int g    = lane >> 2;
    const int t    = lane & 3;
    const int wrow = w * 16;

    // ---- stage Q hi/lo tiles (128 x 64 bf16 each) via cp.async ----
    {
        const int r    = tid >> 1;
        const int half = tid & 1;
        const u16* qgh = Qh + (size_t)(s0 + r) * QDIM + h*HD + half*32;
        const u16* qgl = Ql + (size_t)(s0 + r) * QDIM + h*HD + half*32;
        const uint32_t d = sb + (uint32_t)(r * QSTR + half*64);
        #pragma unroll
        for (int i = 0; i < 4; ++i) {
            cp16(d + 16*i, qgh + 8*i);
            cp16(d + 128*QSTR + 16*i, qgl + 8*i);
        }
        cp_commit();
        cp_wait0();
    }
    __syncthreads();

    // ---- extract Q fragments (A-operand, k16 per kt) ----
    uint32_t qh[4][4], ql[4][4];
    #pragma unroll
    for (int kt = 0; kt < 4; ++kt) {
        uint32_t addr = sb + (uint32_t)((wrow + (lane & 15)) * QSTR) + kt*32 + ((lane >> 4) * 16);
        ldsm4(qh[kt][0], qh[kt][1], qh[kt][2], qh[kt][3], addr);
        ldsm4(ql[kt][0], ql[kt][1], ql[kt][2], ql[kt][3], addr + 128*QSTR);
    }
    __syncthreads();   // Q region reused for K/V below

    float m0 = -CUDART_INF_F, m1 = -CUDART_INF_F;
    float l0 = 0.f, l1 = 0.f;
    float o[8][4];
    #pragma unroll
    for (int nt = 0; nt < 8; ++nt)
        #pragma unroll
        for (int e = 0; e < 4; ++e) o[nt][e] = 0.f;

    const float scale = 0.125f;
    const int kb_end = 2*qi + 2;

    for (int kb = 0; kb < kb_end; ++kb) {
        const int ks0 = kb * 64;

        // ---- K/V tile loads (pure cp.async, pre-split planes) ----
        {
            const int r  = tid >> 2;           // 0..63
            const int q4 = tid & 3;            // 32B quarter
            const u16* kgh = Kh  + (size_t)(ks0 + r) * KVDIM + kvh*HD + q4*16;
            const u16* kgl = Kl  + (size_t)(ks0 + r) * KVDIM + kvh*HD + q4*16;
            const u16* vgh = Vth + (size_t)(kvh*HD + r) * S_LEN + ks0 + q4*16;
            const u16* vgl = Vtl + (size_t)(kvh*HD + r) * S_LEN + ks0 + q4*16;
            const uint32_t d = (uint32_t)(r * QSTR + q4*32);
            cp16(sKH + d, kgh); cp16(sKH + d + 16, kgh + 8);
            cp16(sKL + d, kgl); cp16(sKL + d + 16, kgl + 8);
            cp16(sVH + d, vgh); cp16(sVH + d + 16, vgh + 8);
            cp16(sVL + d, vgl); cp16(sVL + d + 16, vgl + 8);
            cp_commit();
            cp_wait0();
        }
        __syncthreads();

        const bool skip = (ks0 > s0 + wrow + 15);
        if (!skip) {
            // ---- S = Q K^T ----
            float s[8][4];
            #pragma unroll
            for (int nt = 0; nt < 8; ++nt)
                #pragma unroll
                for (int e = 0; e < 4; ++e) s[nt][e] = 0.f;

            #pragma unroll
            for (int kt = 0; kt < 4; ++kt) {
                uint32_t bh[8][2], bl[8][2];
                #pragma unroll
                for (int p = 0; p < 4; ++p) {
                    uint32_t addr = sKH + (uint32_t)((p*16 + (lane & 7) + (((lane >> 4)) << 3)) * QSTR)
                                  + kt*32 + (((lane >> 3) & 1) * 16);
                    ldsm4(bh[2*p][0], bh[2*p][1], bh[2*p+1][0], bh[2*p+1][1], addr);
                    ldsm4(bl[2*p][0], bl[2*p][1], bl[2*p+1][0], bl[2*p+1][1], addr + KVPL);
                }
                #pragma unroll
                for (int nt = 0; nt < 8; ++nt) {
                    mma_bf16(s[nt], qh[kt][0], qh[kt][1], qh[kt][2], qh[kt][3], bh[nt][0], bh[nt][1]);
                    mma_bf16(s[nt], qh[kt][0], qh[kt][1], qh[kt][2], qh[kt][3], bl[nt][0], bl[nt][1]);
                    mma_bf16(s[nt], ql[kt][0], ql[kt][1], ql[kt][2], ql[kt][3], bh[nt][0], bh[nt][1]);
                }
            }

            // ---- scale + causal mask ----
            const bool need_mask = (ks0 + 63 > s0 + wrow);
            const int row0g = s0 + wrow + g;
            #pragma unroll
            for (int nt = 0; nt < 8; ++nt) {
                #pragma unroll
                for (int e = 0; e < 4; ++e) s[nt][e] *= scale;
                if (need_mask) {
                    const int c = ks0 + nt*8 + 2*t;
                    if (c     > row0g    ) s[nt][0] = -CUDART_INF_F;
                    if (c + 1 > row0g    ) s[nt][1] = -CUDART_INF_F;
                    if (c     > row0g + 8) s[nt][2] = -CUDART_INF_F;
                    if (c + 1 > row0g + 8) s[nt][3] = -CUDART_INF_F;
                }
            }

            // ---- online softmax ----
            float mx0 = -CUDART_INF_F, mx1 = -CUDART_INF_F;
            #pragma unroll
            for (int nt = 0; nt < 8; ++nt) {
                mx0 = fmaxf(mx0, fmaxf(s[nt][0], s[nt][1]));
                mx1 = fmaxf(mx1, fmaxf(s[nt][2], s[nt][3]));
            }
            mx0 = fmaxf(mx0, __shfl_xor_sync(0xffffffffu, mx0, 1));
            mx0 = fmaxf(mx0, __shfl_xor_sync(0xffffffffu, mx0, 2));
            mx1 = fmaxf(mx1, __shfl_xor_sync(0xffffffffu, mx1, 1));
            mx1 = fmaxf(mx1, __shfl_xor_sync(0xffffffffu, mx1, 2));

            float mn0 = fmaxf(m0, mx0), mn1 = fmaxf(m1, mx1);
            float corr0 = __expf(m0 - mn0), corr1 = __expf(m1 - mn1);

            float ps0 = 0.f, ps1 = 0.f;
            #pragma unroll
            for (int nt = 0; nt < 8; ++nt) {
                s[nt][0] = __expf(s[nt][0] - mn0);
                s[nt][1] = __expf(s[nt][1] - mn0);
                s[nt][2] = __expf(s[nt][2] - mn1);
                s[nt][3] = __expf(s[nt][3] - mn1);
                ps0 += s[nt][0] + s[nt][1];
                ps1 += s[nt][2] + s[nt][3];
            }
            ps0 += __shfl_xor_sync(0xffffffffu, ps0, 1);
            ps0 += __shfl_xor_sync(0xffffffffu, ps0, 2);
            ps1 += __shfl_xor_sync(0xffffffffu, ps1, 1);
            ps1 += __shfl_xor_sync(0xffffffffu, ps1, 2);

            l0 = l0 * corr0 + ps0;  m0 = mn0;
            l1 = l1 * corr1 + ps1;  m1 = mn1;

            #pragma unroll
            for (int nt = 0; nt < 8; ++nt) {
                o[nt][0] *= corr0; o[nt][1] *= corr0;
                o[nt][2] *= corr1; o[nt][3] *= corr1;
            }

            // ---- PV: P C-frag -> k16 A-frag directly; V frags via ldmatrix ----
            #pragma unroll
            for (int kt = 0; kt < 4; ++kt) {
                float r0, r1;
                uint32_t ah0 = bfsplit2(s[2*kt  ][0], s[2*kt  ][1], r0, r1);
                uint32_t al0 = bfpack2(r0, r1);
                uint32_t ah1 = bfsplit2(s[2*kt  ][2], s[2*kt  ][3], r0, r1);
                uint32_t al1 = bfpack2(r0, r1);
                uint32_t ah2 = bfsplit2(s[2*kt+1][0], s[2*kt+1][1], r0, r1);
                uint32_t al2 = bfpack2(r0, r1);
                uint32_t ah3 = bfsplit2(s[2*kt+1][2], s[2*kt+1][3], r0, r1);
                uint32_t al3 = bfpack2(r0, r1);

                uint32_t vh[8][2], vl[8][2];
                #pragma unroll
                for (int p = 0; p < 4; ++p) {
                    uint32_t addr = sVH + (uint32_t)((p*16 + (lane & 7) + (((lane >> 4)) << 3)) * QSTR)
                                  + kt*32 + (((lane >> 3) & 1) * 16);
                    ldsm4(vh[2*p][0], vh[2*p][1], vh[2*p+1][0], vh[2*p+1][1], addr);
                    ldsm4(vl[2*p][0], vl[2*p][1], vl[2*p+1][0], vl[2*p+1][1], addr + KVPL);
                }
                #pragma unroll
                for (int nt = 0; nt < 8; ++nt) {
                    mma_bf16(o[nt], ah0, ah1, ah2, ah3, vh[nt][0], vh[nt][1]);
                    mma_bf16(o[nt], ah0, ah1, ah2, ah3, vl[nt][0], vl[nt][1]);
                    mma_bf16(o[nt], al0, al1, al2, al3, vh[nt][0], vh[nt][1]);
                }
            }
        }
        __syncthreads();
    }

    // ---- epilogue: sink-LSE renorm + split-store AO planes ----
    const float sink = sinks[h];
    float lse0 = m0 + __logf(l0);
    float lse1 = m1 + __logf(l1);
    float cb0 = fmaxf(lse0, sink) + log1pf(__expf(-fabsf(lse0 - sink)));
    float cb1 = fmaxf(lse1, sink) + log1pf(__expf(-fabsf(lse1 - sink)));
    float inv0 = __expf(fmaxf(lse0 - cb0, -20.f)) / l0;
    float inv1 = __expf(fmaxf(lse1 - cb1, -20.f)) / l1;

    const int r0i = s0 + wrow + g;
    #pragma unroll
    for (int nt = 0; nt < 8; ++nt) {
        const int c = h*HD + nt*8 + 2*t;
        const size_t i0 = (size_t)r0i * QDIM + c;
        const size_t i1 = (size_t)(r0i + 8) * QDIM + c;
        float lr0, lr1;
        float v00 = o[nt][0] * inv0, v01 = o[nt][1] * inv0;
        float v10 = o[nt][2] * inv1, v11 = o[nt][3] * inv1;
        u16 h00 = bf_hi(v00, lr0); u16 h01 = bf_hi(v01, lr1);
        *(uint32_t*)(AOh + i0) = (uint32_t)h00 | ((uint32_t)h01 << 16);
        *(uint32_t*)(AOl + i0) = (uint32_t)tobf(lr0) | ((uint32_t)tobf(lr1) << 16);
        u16 h10 = bf_hi(v10, lr0); u16 h11 = bf_hi(v11, lr1);
        *(uint32_t*)(AOh + i1) = (uint32_t)h10 | ((uint32_t)h11 << 16);
        *(uint32_t*)(AOl + i1) = (uint32_t)tobf(lr0) | ((uint32_t)tobf(lr1) << 16);
    }
}

// ---------------------------------------------------------------------------
// Launch
// ---------------------------------------------------------------------------
extern "C" void kernel_launch(void* const* d_in, const int* in_sizes, int n_in,
                              void* d_out, int out_size)
{
    const float* x     = (const float*)d_in[0];
    const float* rope  = (const float*)d_in[1];
    const float* wq_w  = (const float*)d_in[2];
    const float* wq_b  = (const float*)d_in[3];
    const float* wk_w  = (const float*)d_in[4];
    const float* wk_b  = (const float*)d_in[5];
    const float* wv_w  = (const float*)d_in[6];
    const float* wv_b  = (const float*)d_in[7];
    const float* wo_w  = (const float*)d_in[8];
    const float* wo_b  = (const float*)d_in[9];
    const float* sinks = (const float*)d_in[10];
    float* out = (float*)d_out;

#define SYM(p, s) do { void* _q; cudaGetSymbolAddress(&_q, s); p = decltype(p)(_q); } while (0)
    float *Q, *K;
    u16 *Qh,*Ql,*Kh,*Kl,*Vth,*Vtl,*AOh,*AOl,*xh,*xl,*wqh,*wql,*wkh,*wkl,*wvh,*wvl,*woh,*wol;
    SYM(Q, g_Q);   SYM(K, g_K);
    SYM(Qh, g_Qh); SYM(Ql, g_Ql); SYM(Kh, g_Kh); SYM(Kl, g_Kl);
    SYM(Vth, g_Vth); SYM(Vtl, g_Vtl);
    SYM(AOh, g_AOh); SYM(AOl, g_AOl);
    SYM(xh, g_xh); SYM(xl, g_xl);
    SYM(wqh, g_wqh); SYM(wql, g_wql);
    SYM(wkh, g_wkh); SYM(wkl, g_wkl);
    SYM(wvh, g_wvh); SYM(wvl, g_wvl);
    SYM(woh, g_woh); SYM(wol, g_wol);
#undef SYM

    cudaFuncSetAttribute(gemm_bf3, cudaFuncAttributeMaxDynamicSharedMemorySize, GEMM_DYN);

    // split inputs to bf16 hi/lo planes
    split_kernel<<<(S_LEN*DIM/4 + 255)/256, 256>>>(x,    xh,  xl,  S_LEN*DIM/4);
    split_kernel<<<(QDIM*DIM/4  + 255)/256, 256>>>(wq_w, wqh, wql, QDIM*DIM/4);
    split_kernel<<<(KVDIM*DIM/4 + 255)/256, 256>>>(wk_w, wkh, wkl, KVDIM*DIM/4);
    split_kernel<<<(KVDIM*DIM/4 + 255)/256, 256>>>(wv_w, wvh, wvl, KVDIM*DIM/4);
    split_kernel<<<(DIM*QDIM/4  + 255)/256, 256>>>(wo_w, woh, wol, DIM*QDIM/4);

    // projections
    gemm_bf3<<<dim3(QDIM/128,  S_LEN/128), 256, GEMM_DYN>>>(xh, xl, wqh, wql, wq_b, Q, nullptr, nullptr, DIM, QDIM, 0);
    gemm_bf3<<<dim3(KVDIM/128, S_LEN/128), 256, GEMM_DYN>>>(xh, xl, wkh, wkl, wk_b, K, nullptr, nullptr, DIM, KVDIM, 0);
    gemm_bf3<<<dim3(KVDIM/128, S_LEN/128), 256, GEMM_DYN>>>(xh, xl, wvh, wvl, wv_b, nullptr, Vth, Vtl, DIM, KVDIM, 2);

    // rope + split
    rope_split_kernel<<<(S_LEN*NH  *32)/256, 256>>>(Q, rope, Qh, Ql, NH,   QDIM);
    rope_split_kernel<<<(S_LEN*NKVH*32)/256, 256>>>(K, rope, Kh, Kl, NKVH, KVDIM);

    // attention
    attn_kernel<<<dim3(S_LEN/128, NH), 256, ATT_DYN>>>(Qh, Ql, Kh, Kl, Vth, Vtl, sinks, AOh, AOl);

    // output projection
    gemm_bf3<<<dim3(DIM/128, S_LEN/128), 256, GEMM_DYN>>>(AOh, AOl, woh, wol, wo_b, out, nullptr, nullptr, QDIM, DIM, 0);
}